// round 10
// baseline (speedup 1.0000x reference)
#include <cuda_runtime.h>
#include <cuda_bf16.h>
#include <cstdint>
#include <math.h>

#define T 2048
#define HID 1280
#define NH 16
#define HD 80
#define THID (3*HID)

// ---------------- scratch (static device allocations only) ----------------
__device__ float g_qkv[T*THID];

__device__ __nv_bfloat16 g_xh[T*HID],    g_xl[T*HID];
__device__ __nv_bfloat16 g_wqh[THID*HID], g_wql[THID*HID];
__device__ __nv_bfloat16 g_wph[HID*HID],  g_wpl[HID*HID];
__device__ __nv_bfloat16 g_ah[T*HID],    g_al[T*HID];

// bf16 hi/lo roped Q,K and V, per head: [head][T][80]
__device__ __nv_bfloat16 g_qh[NH*T*HD], g_ql[NH*T*HD];
__device__ __nv_bfloat16 g_kh[NH*T*HD], g_kl[NH*T*HD];
__device__ __nv_bfloat16 g_vh[NH*T*HD], g_vl[NH*T*HD];

// ---------------- helpers ----------------
__device__ __forceinline__ uint32_t smem_to_u32(const void* p) {
    uint32_t a;
    asm("{ .reg .u64 tmp; cvta.to.shared.u64 tmp, %1; cvt.u32.u64 %0, tmp; }"
        : "=r"(a) : "l"(p));
    return a;
}
__device__ __forceinline__ void mma_bf16(float* c, const uint32_t* a, const uint32_t* b) {
    asm volatile("mma.sync.aligned.m16n8k16.row.col.f32.bf16.bf16.f32 "
        "{%0,%1,%2,%3}, {%4,%5,%6,%7}, {%8,%9}, {%0,%1,%2,%3};"
        : "+f"(c[0]), "+f"(c[1]), "+f"(c[2]), "+f"(c[3])
        : "r"(a[0]), "r"(a[1]), "r"(a[2]), "r"(a[3]), "r"(b[0]), "r"(b[1]));
}
__device__ __forceinline__ void ldsm_x4(uint32_t* r, uint32_t addr) {
    asm volatile("ldmatrix.sync.aligned.m8n8.x4.shared.b16 {%0,%1,%2,%3}, [%4];"
        : "=r"(r[0]), "=r"(r[1]), "=r"(r[2]), "=r"(r[3]) : "r"(addr));
}
__device__ __forceinline__ void ldsm_x4_t(uint32_t* r, uint32_t addr) {
    asm volatile("ldmatrix.sync.aligned.m8n8.x4.trans.shared.b16 {%0,%1,%2,%3}, [%4];"
        : "=r"(r[0]), "=r"(r[1]), "=r"(r[2]), "=r"(r[3]) : "r"(addr));
}
__device__ __forceinline__ void cp_async16(uint32_t dst, const void* src) {
    asm volatile("cp.async.cg.shared.global [%0], [%1], 16;" :: "r"(dst), "l"(src));
}
#define CP_COMMIT() asm volatile("cp.async.commit_group;" ::: "memory")
#define CP_WAIT1()  asm volatile("cp.async.wait_group 1;" ::: "memory")
__device__ __forceinline__ uint32_t packbf(float lo_, float hi_) {
    uint32_t r;
    asm("cvt.rn.bf16x2.f32 %0, %1, %2;" : "=r"(r) : "f"(hi_), "f"(lo_));
    return r;
}

// ---------------------------------------------------------------------------
// fp32 -> bf16 hi + lo split (x input)
// ---------------------------------------------------------------------------
__global__ void convert_split_kernel(const float* __restrict__ src,
                                     __nv_bfloat16* __restrict__ h,
                                     __nv_bfloat16* __restrict__ l, int n)
{
    int i = blockIdx.x * blockDim.x + threadIdx.x;
    if (i >= n) return;
    float v = src[i];
    __nv_bfloat16 hh = __float2bfloat16_rn(v);
    h[i] = hh;
    l[i] = __float2bfloat16_rn(v - __bfloat162float(hh));
}

__global__ void convert_splitT_kernel(const float* __restrict__ src,
                                      __nv_bfloat16* __restrict__ h,
                                      __nv_bfloat16* __restrict__ l,
                                      int K, int N)
{
    __shared__ float t[32][33];
    int nb = blockIdx.x * 32, kb = blockIdx.y * 32;
    int tx = threadIdx.x, ty = threadIdx.y;
    #pragma unroll
    for (int j = 0; j < 4; j++)
        t[ty + j * 8][tx] = src[(size_t)(kb + ty + j * 8) * N + nb + tx];
    __syncthreads();
    #pragma unroll
    for (int j = 0; j < 4; j++) {
        float v = t[tx][ty + j * 8];
        __nv_bfloat16 hh = __float2bfloat16_rn(v);
        size_t o = (size_t)(nb + ty + j * 8) * K + kb + tx;
        h[o] = hh;
        l[o] = __float2bfloat16_rn(v - __bfloat162float(hh));
    }
}

// ---------------------------------------------------------------------------
// Split-bf16 tensor-core GEMM via mma.sync.
// Round 10: 3-stage cp.async ring, ONE __syncthreads per K-iter.
// Loads for stage it+2 are issued immediately after the barrier so they
// overlap the whole compute of stage it. Stage being overwritten was last
// read at iter it-1, protected by the iter-it barrier.
// ---------------------------------------------------------------------------
#define BM 64
#define BN 128
#define BK 32
#define ASTRIDE 40                       // bf16 per smem row (80B)
#define A_TILE (64*80)                   // 5120 B
#define B_TILE (128*80)                  // 10240 B
#define STAGE_B (2*A_TILE + 2*B_TILE)    // 30720 B
#define NSTAGE 3
#define GEMM_SMEM (NSTAGE*STAGE_B)       // 92160 B

__global__ __launch_bounds__(256, 2)
void gemm_bf16split_kernel(const __nv_bfloat16* __restrict__ Ah,
                           const __nv_bfloat16* __restrict__ Al,
                           const __nv_bfloat16* __restrict__ Bh,
                           const __nv_bfloat16* __restrict__ Bl,
                           const float* __restrict__ bias,
                           float* __restrict__ C,
                           int M, int N, int K)
{
    extern __shared__ char sm[];
    const uint32_t sbase = smem_to_u32(sm);

    const int tid  = threadIdx.x;
    const int wid  = tid >> 5;
    const int lane = tid & 31;
    const int m0 = blockIdx.y * BM, n0 = blockIdx.x * BN;
    const int wm = (wid >> 1) * 16;
    const int wn = (wid & 1) * 64;

    float acc[8][4];
    #pragma unroll
    for (int b = 0; b < 8; b++)
        #pragma unroll
        for (int c = 0; c < 4; c++) acc[b][c] = 0.f;

    const int c_row = tid >> 2;            // 0..63
    const int c_col = (tid & 3) * 8;       // bf16 col 0,8,16,24
    const uint32_t s_off  = (uint32_t)(c_row * ASTRIDE + c_col) * 2;
    const uint32_t s_off2 = s_off + (uint32_t)64 * ASTRIDE * 2;

    const __nv_bfloat16* gAh = Ah + (size_t)(m0 + c_row) * K + c_col;
    const __nv_bfloat16* gAl = Al + (size_t)(m0 + c_row) * K + c_col;
    const __nv_bfloat16* gBh = Bh + (size_t)(n0 + c_row) * K + c_col;
    const __nv_bfloat16* gBl = Bl + (size_t)(n0 + c_row) * K + c_col;
    const size_t g2 = (size_t)64 * K;

    const int niter = K / BK;

    // prologue: stages 0 and 1
    #pragma unroll
    for (int s = 0; s < 2; s++) {
        uint32_t sb = sbase + s * STAGE_B;
        int k0 = s * BK;
        cp_async16(sb + s_off,                      gAh + k0);
        cp_async16(sb + A_TILE + s_off,             gAl + k0);
        cp_async16(sb + 2*A_TILE + s_off,           gBh + k0);
        cp_async16(sb + 2*A_TILE + s_off2,          gBh + g2 + k0);
        cp_async16(sb + 2*A_TILE + B_TILE + s_off,  gBl + k0);
        cp_async16(sb + 2*A_TILE + B_TILE + s_off2, gBl + g2 + k0);
        CP_COMMIT();
    }

    const int a_row  = (lane & 15);
    const int a_colb = (lane >> 4) * 16;
    const int b_row  = (lane & 7) + ((lane >> 4) << 3);
    const int b_colb = (((lane >> 3) & 1)) * 16;

    int stage = 0;
    for (int it = 0; it < niter; it++) {
        CP_WAIT1();                 // stage `it` complete (per-thread)
        __syncthreads();            // all threads' waits done -> data visible;
                                    // also: everyone finished reading iter it-1

        // issue stage it+2 (overwrites the stage read at iter it-1)
        int nk = it + 2;
        if (nk < niter) {
            int ns = stage + 2; if (ns >= NSTAGE) ns -= NSTAGE;
            uint32_t sb = sbase + ns * STAGE_B;
            int k0 = nk * BK;
            cp_async16(sb + s_off,                      gAh + k0);
            cp_async16(sb + A_TILE + s_off,             gAl + k0);
            cp_async16(sb + 2*A_TILE + s_off,           gBh + k0);
            cp_async16(sb + 2*A_TILE + s_off2,          gBh + g2 + k0);
            cp_async16(sb + 2*A_TILE + B_TILE + s_off,  gBl + k0);
            cp_async16(sb + 2*A_TILE + B_TILE + s_off2, gBl + g2 + k0);
        }
        CP_COMMIT();                // commit even if empty: keeps group count in sync

        const uint32_t sb  = sbase + stage * STAGE_B;
        const uint32_t sAh = sb;
        const uint32_t sAl = sb + A_TILE;
        const uint32_t sBh = sb + 2*A_TILE;
        const uint32_t sBl = sb + 2*A_TILE + B_TILE;

        #pragma unroll
        for (int k16 = 0; k16 < 2; k16++) {
            const int kcb = k16 * 32;
            uint32_t ah[4], al[4];
            {
                uint32_t ro = (uint32_t)(wm + a_row) * 80 + kcb + a_colb;
                ldsm_x4(ah, sAh + ro);
                ldsm_x4(al, sAl + ro);
            }
            #pragma unroll
            for (int g = 0; g < 4; g++) {
                uint32_t ro = (uint32_t)(wn + g*16 + b_row) * 80 + kcb + b_colb;
                uint32_t bh[4], bl[4];
                ldsm_x4(bh, sBh + ro);
                ldsm_x4(bl, sBl + ro);
                mma_bf16(acc[g*2+0], ah, bh + 0);
                mma_bf16(acc[g*2+1], ah, bh + 2);
                mma_bf16(acc[g*2+0], ah, bl + 0);
                mma_bf16(acc[g*2+1], ah, bl + 2);
                mma_bf16(acc[g*2+0], al, bh + 0);
                mma_bf16(acc[g*2+1], al, bh + 2);
            }
        }
        if (++stage == NSTAGE) stage = 0;
    }

    // Epilogue
    {
        int r0 = m0 + wm + (lane >> 2);
        #pragma unroll
        for (int t = 0; t < 8; t++) {
            int col = n0 + wn + t*8 + (lane & 3)*2;
            float b0 = bias[col], b1 = bias[col + 1];
            float2 v0 = { acc[t][0] + b0, acc[t][1] + b1 };
            float2 v1 = { acc[t][2] + b0, acc[t][3] + b1 };
            *(float2*)(C + (size_t)r0 * N + col)       = v0;
            *(float2*)(C + (size_t)(r0 + 8) * N + col) = v1;
        }
    }
}

// ---------------------------------------------------------------------------
// RoPE + split qkv into per-head bf16 hi/lo Q,K,V buffers [head][T][80].
// ---------------------------------------------------------------------------
__global__ void rope_split_kernel(const float* __restrict__ rope)
{
    int idx = blockIdx.x * blockDim.x + threadIdx.x;
    if (idx >= T * NH * HD) return;
    int d = idx % HD;
    int n = (idx / HD) % NH;
    int t = idx / (HD * NH);

    int dr = (d < 40) ? d : d - 40;
    float ang = rope[t * 40 + dr];
    float c = cosf(ang), s = sinf(ang);

    const float* qrow = g_qkv + (size_t)t * THID + n * HD;
    float qv, kv;
    if (d < 40) {
        qv = qrow[d] * c        - qrow[d + 40] * s;
        kv = qrow[HID + d] * c  - qrow[HID + d + 40] * s;
    } else {
        qv = qrow[d - 40] * s       + qrow[d] * c;
        kv = qrow[HID + d - 40] * s + qrow[HID + d] * c;
    }
    float vv = qrow[2 * HID + d];
    int o = (n * T + t) * HD + d;
    __nv_bfloat16 h;
    h = __float2bfloat16_rn(qv); g_qh[o] = h; g_ql[o] = __float2bfloat16_rn(qv - __bfloat162float(h));
    h = __float2bfloat16_rn(kv); g_kh[o] = h; g_kl[o] = __float2bfloat16_rn(kv - __bfloat162float(h));
    h = __float2bfloat16_rn(vv); g_vh[o] = h; g_vl[o] = __float2bfloat16_rn(vv - __bfloat162float(h));
}

// ---------------------------------------------------------------------------
// Tensor-core flash attention with block-diagonal masking (proven round 8).
// ---------------------------------------------------------------------------
#define KVSB 176
#define STG  22528

__device__ __forceinline__ void attn_prefetch(char* sm_, int sbuf, int n, int kb,
                                              const int* __restrict__ seg,
                                              int tid, int* segk)
{
    char* dst = sm_ + sbuf * STG;
    #pragma unroll
    for (int i = 0; i < 10; i++) {
        int c = tid + i * 128;
        int arr = c / 320, w = c % 320;
        int key = w / 10, cb = (w % 10) * 16;
        int kg = kb + key;
        uint4 v = make_uint4(0u, 0u, 0u, 0u);
        const __nv_bfloat16* base = (arr == 0) ? g_kh : (arr == 1) ? g_kl
                                  : (arr == 2) ? g_vh : g_vl;
        if (kg < T)
            v = *(const uint4*)((const char*)(base + (size_t)(n * T + kg) * HD) + cb);
        *(uint4*)(dst + arr * 5632 + key * KVSB + cb) = v;
    }
    if (tid < 32) segk[sbuf * 32 + tid] = (kb + tid < T) ? seg[kb + tid] : -1;
}

__global__ __launch_bounds__(128)
void attn_mma_kernel(const int* __restrict__ seg)
{
    __shared__ __align__(16) char sm_[2 * STG + 256];
    int* segk = (int*)(sm_ + 2 * STG);
    const uint32_t sb0 = smem_to_u32(sm_);

    const int n = blockIdx.y;
    const int q0 = blockIdx.x * 64;
    const int tid = threadIdx.x;
    const int lane = tid & 31;
    const int wid = tid >> 5;
    const int wr = wid * 16;

    const int seg_lo = seg[q0], seg_hi = seg[q0 + 63];
    int lo = 0, hi = T;
    while (lo < hi) { int mid = (lo + hi) >> 1; if (seg[mid] < seg_lo) lo = mid + 1; else hi = mid; }
    const int kstart = lo;
    hi = T;
    while (lo < hi) { int mid = (lo + hi) >> 1; if (seg[mid] <= seg_hi) lo = mid + 1; else hi = mid; }
    const int kend = lo;
    const int kb0 = kstart & ~31;
    const int n_tiles = (kend - kb0 + 31) >> 5;

    const int myseg0 = seg[q0 + wr + (lane >> 2)];
    const int myseg1 = seg[q0 + wr + (lane >> 2) + 8];

    {
        const char* gq_h = (const char*)(g_qh + (size_t)(n * T + q0) * HD);
        const char* gq_l = (const char*)(g_ql + (size_t)(n * T + q0) * HD);
        #pragma unroll
        for (int i = 0; i < 5; i++) {
            int c = tid + i * 128;
            int row = c / 10, cb = (c % 10) * 16;
            *(uint4*)(sm_ + STG + row * KVSB + cb)         = *(const uint4*)(gq_h + row * 160 + cb);
            *(uint4*)(sm_ + STG + 11264 + row * KVSB + cb) = *(const uint4*)(gq_l + row * 160 + cb);
        }
    }
    attn_prefetch(sm_, 0, n, kb0, seg, tid, segk);
    __syncthreads();

    uint32_t qfh[5][4], qfl[5][4];
    {
        uint32_t base_h = sb0 + STG + (uint32_t)(wr + (lane & 15)) * KVSB + ((lane >> 4) * 8) * 2;
        uint32_t base_l = base_h + 11264;
        #pragma unroll
        for (int ks = 0; ks < 5; ks++) {
            ldsm_x4(qfh[ks], base_h + ks * 32);
            ldsm_x4(qfl[ks], base_l + ks * 32);
        }
    }
    __syncthreads();

    float OC[10][4];
    #pragma unroll
    for (int i = 0; i < 10; i++) { OC[i][0] = OC[i][1] = OC[i][2] = OC[i][3] = 0.f; }
    float m0 = -1e30f, m1 = -1e30f, l0 = 0.f, l1 = 0.f;
    const float scale = 0.11180339887498949f;

    for (int t = 0; t < n_tiles; t++) {
        if (t + 1 < n_tiles) attn_prefetch(sm_, (t + 1) & 1, n, kb0 + (t + 1) * 32, seg, tid, segk);
        const uint32_t sb = sb0 + (t & 1) * STG;
        const int* sgk = segk + (t & 1) * 32;

        float SC[4][4];
        #pragma unroll
        for (int g = 0; g < 4; g++) SC[g][0] = SC[g][1] = SC[g][2] = SC[g][3] = 0.f;

        const int krow = ((lane & 16) >> 1) + (lane & 7);
        #pragma unroll
        for (int ks = 0; ks < 5; ks++) {
            const int dimb = (ks * 16 + ((lane >> 3) & 1) * 8) * 2;
            #pragma unroll
            for (int gp = 0; gp < 2; gp++) {
                uint32_t kh[4], kl[4];
                uint32_t a = sb + (uint32_t)(16 * gp + krow) * KVSB + dimb;
                ldsm_x4(kh, a);
                ldsm_x4(kl, a + 5632);
                #pragma unroll
                for (int h = 0; h < 2; h++) {
                    int g = 2 * gp + h;
                    mma_bf16(SC[g], qfh[ks], kh + 2 * h);
                    mma_bf16(SC[g], qfh[ks], kl + 2 * h);
                    mma_bf16(SC[g], qfl[ks], kh + 2 * h);
                }
            }
        }

        float sM[4][4];
        #pragma unroll
        for (int g = 0; g < 4; g++) {
            int k0i = 8 * g + 2 * (lane & 3);
            int sA = sgk[k0i], sB = sgk[k0i + 1];
            sM[g][0] = (sA == myseg0) ? SC[g][0] * scale : -1e30f;
            sM[g][1] = (sB == myseg0) ? SC[g][1] * scale : -1e30f;
            sM[g][2] = (sA == myseg1) ? SC[g][2] * scale : -1e30f;
            sM[g][3] = (sB == myseg1) ? SC[g][3] * scale : -1e30f;
        }
        float cm0 = -1e30f, cm1 = -1e30f;
        #pragma unroll
        for (int g = 0; g < 4; g++) {
            cm0 = fmaxf(cm0, fmaxf(sM[g][0], sM[g][1]));
            cm1 = fmaxf(cm1, fmaxf(sM[g][2], sM[g][3]));
        }
        cm0 = fmaxf(cm0, __shfl_xor_sync(0xffffffffu, cm0, 1));
        cm0 = fmaxf(cm0, __shfl_xor_sync(0xffffffffu, cm0, 2));
        cm1 = fmaxf(cm1, __shfl_xor_sync(0xffffffffu, cm1, 1));
        cm1 = fmaxf(cm1, __shfl_xor_sync(0xffffffffu, cm1, 2));
        float nm0 = fmaxf(m0, cm0), nm1 = fmaxf(m1, cm1);
        float f0 = __expf(m0 - nm0), f1 = __expf(m1 - nm1);
        m0 = nm0; m1 = nm1;
        l0 *= f0; l1 *= f1;
        #pragma unroll
        for (int i = 0; i < 10; i++) {
            OC[i][0] *= f0; OC[i][1] *= f0; OC[i][2] *= f1; OC[i][3] *= f1;
        }

        float p[4][4];
        #pragma unroll
        for (int g = 0; g < 4; g++) {
            p[g][0] = __expf(sM[g][0] - m0); p[g][1] = __expf(sM[g][1] - m0);
            p[g][2] = __expf(sM[g][2] - m1); p[g][3] = __expf(sM[g][3] - m1);
            l0 += p[g][0] + p[g][1];
            l1 += p[g][2] + p[g][3];
        }

        uint32_t pah[2][4], pal[2][4];
        #pragma unroll
        for (int ks2 = 0; ks2 < 2; ks2++) {
            #pragma unroll
            for (int pos = 0; pos < 4; pos++) {
                int g = 2 * ks2 + (pos >> 1);
                int e = (pos & 1) * 2;
                float x0 = p[g][e], x1 = p[g][e + 1];
                float h0 = __bfloat162float(__float2bfloat16_rn(x0));
                float h1 = __bfloat162float(__float2bfloat16_rn(x1));
                pah[ks2][pos] = packbf(h0, h1);
                pal[ks2][pos] = packbf(x0 - h0, x1 - h1);
            }
        }

        #pragma unroll
        for (int ks2 = 0; ks2 < 2; ks2++) {
            const int vkey = 16 * ks2 + (lane & 15);
            const int vhalf = ((lane >> 4) & 1) * 16;
            #pragma unroll
            for (int dp = 0; dp < 5; dp++) {
                uint32_t vh[4], vl[4];
                uint32_t a = sb + 11264 + (uint32_t)vkey * KVSB + dp * 32 + vhalf;
                ldsm_x4_t(vh, a);
                ldsm_x4_t(vl, a + 5632);
                mma_bf16(OC[2*dp],     pah[ks2], vh + 0);
                mma_bf16(OC[2*dp],     pah[ks2], vl + 0);
                mma_bf16(OC[2*dp],     pal[ks2], vh + 0);
                mma_bf16(OC[2*dp + 1], pah[ks2], vh + 2);
                mma_bf16(OC[2*dp + 1], pah[ks2], vl + 2);
                mma_bf16(OC[2*dp + 1], pal[ks2], vh + 2);
            }
        }
        __syncthreads();
    }

    l0 += __shfl_xor_sync(0xffffffffu, l0, 1);
    l0 += __shfl_xor_sync(0xffffffffu, l0, 2);
    l1 += __shfl_xor_sync(0xffffffffu, l1, 1);
    l1 += __shfl_xor_sync(0xffffffffu, l1, 2);
    float inv0 = 1.f / l0, inv1 = 1.f / l1;
    const int row0 = q0 + wr + (lane >> 2);
    const int colb = n * HD + 2 * (lane & 3);
    #pragma unroll
    for (int ng = 0; ng < 10; ng++) {
        int col = colb + 8 * ng;
        float v0 = OC[ng][0] * inv0, v1 = OC[ng][1] * inv0;
        float v2 = OC[ng][2] * inv1, v3 = OC[ng][3] * inv1;
        float h0 = __bfloat162float(__float2bfloat16_rn(v0));
        float h1 = __bfloat162float(__float2bfloat16_rn(v1));
        float h2 = __bfloat162float(__float2bfloat16_rn(v2));
        float h3 = __bfloat162float(__float2bfloat16_rn(v3));
        *(uint32_t*)(g_ah + (size_t)row0 * HID + col)       = packbf(h0, h1);
        *(uint32_t*)(g_al + (size_t)row0 * HID + col)       = packbf(v0 - h0, v1 - h1);
        *(uint32_t*)(g_ah + (size_t)(row0 + 8) * HID + col) = packbf(h2, h3);
        *(uint32_t*)(g_al + (size_t)(row0 + 8) * HID + col) = packbf(v2 - h2, v3 - h3);
    }
}

// ---------------------------------------------------------------------------
extern "C" void kernel_launch(void* const* d_in, const int* in_sizes, int n_in,
                              void* d_out, int out_size)
{
    const float* x     = (const float*)d_in[0];
    const float* rope  = (const float*)d_in[1];
    const int*   seg   = (const int*)  d_in[2];
    const float* qkvW  = (const float*)d_in[3];
    const float* qkvB  = (const float*)d_in[4];
    const float* projW = (const float*)d_in[5];
    const float* projB = (const float*)d_in[6];
    float* out = (float*)d_out;

    float* p_qkv;
    cudaGetSymbolAddress((void**)&p_qkv, g_qkv);
    __nv_bfloat16 *p_xh, *p_xl, *p_wqh, *p_wql, *p_wph, *p_wpl, *p_ah, *p_al;
    cudaGetSymbolAddress((void**)&p_xh, g_xh);   cudaGetSymbolAddress((void**)&p_xl, g_xl);
    cudaGetSymbolAddress((void**)&p_wqh, g_wqh); cudaGetSymbolAddress((void**)&p_wql, g_wql);
    cudaGetSymbolAddress((void**)&p_wph, g_wph); cudaGetSymbolAddress((void**)&p_wpl, g_wpl);
    cudaGetSymbolAddress((void**)&p_ah, g_ah);   cudaGetSymbolAddress((void**)&p_al, g_al);

    cudaFuncSetAttribute(gemm_bf16split_kernel,
                         cudaFuncAttributeMaxDynamicSharedMemorySize, GEMM_SMEM);

    // 0. convert inputs to split-bf16 (weights transposed to [N][K])
    convert_split_kernel<<<(T*HID + 255)/256, 256>>>(x, p_xh, p_xl, T*HID);
    convert_splitT_kernel<<<dim3(THID/32, HID/32), dim3(32, 8)>>>(qkvW, p_wqh, p_wql, HID, THID);
    convert_splitT_kernel<<<dim3(HID/32, HID/32), dim3(32, 8)>>>(projW, p_wph, p_wpl, HID, HID);

    // 1. qkv = x @ Wqkv + b   (mma.sync split-bf16, 3-stage pipeline)
    gemm_bf16split_kernel<<<dim3(THID/BN, T/BM), 256, GEMM_SMEM>>>(
        p_xh, p_xl, p_wqh, p_wql, qkvB, p_qkv, T, THID, HID);

    // 2. RoPE + split into per-head bf16 hi/lo Q,K,V
    rope_split_kernel<<<(T*NH*HD + 255)/256, 256>>>(rope);

    // 3. Tensor-core block-diagonal flash attention -> bf16 hi/lo att
    attn_mma_kernel<<<dim3(T/64, NH), 128>>>(seg);

    // 4. out = att @ Wproj + b
    gemm_bf16split_kernel<<<dim3(HID/BN, T/BM), 256, GEMM_SMEM>>>(
        p_ah, p_al, p_wph, p_wpl, projB, out, T, HID, HID);
}

// round 11
// speedup vs baseline: 1.0113x; 1.0113x over previous
#include <cuda_runtime.h>
#include <cuda_bf16.h>
#include <cstdint>
#include <math.h>

#define T 2048
#define HID 1280
#define NH 16
#define HD 80
#define THID (3*HID)

// ---------------- scratch (static device allocations only) ----------------
__device__ float g_qkv[T*THID];

__device__ __nv_bfloat16 g_xh[T*HID],    g_xl[T*HID];
__device__ __nv_bfloat16 g_wqh[THID*HID], g_wql[THID*HID];
__device__ __nv_bfloat16 g_wph[HID*HID],  g_wpl[HID*HID];
__device__ __nv_bfloat16 g_ah[T*HID],    g_al[T*HID];

// bf16 hi/lo roped Q,K and V, per head: [head][T][80]
__device__ __nv_bfloat16 g_qh[NH*T*HD], g_ql[NH*T*HD];
__device__ __nv_bfloat16 g_kh[NH*T*HD], g_kl[NH*T*HD];
__device__ __nv_bfloat16 g_vh[NH*T*HD], g_vl[NH*T*HD];

// ---------------- helpers ----------------
__device__ __forceinline__ uint32_t smem_to_u32(const void* p) {
    uint32_t a;
    asm("{ .reg .u64 tmp; cvta.to.shared.u64 tmp, %1; cvt.u32.u64 %0, tmp; }"
        : "=r"(a) : "l"(p));
    return a;
}
__device__ __forceinline__ void mma_bf16(float* c, const uint32_t* a, const uint32_t* b) {
    asm volatile("mma.sync.aligned.m16n8k16.row.col.f32.bf16.bf16.f32 "
        "{%0,%1,%2,%3}, {%4,%5,%6,%7}, {%8,%9}, {%0,%1,%2,%3};"
        : "+f"(c[0]), "+f"(c[1]), "+f"(c[2]), "+f"(c[3])
        : "r"(a[0]), "r"(a[1]), "r"(a[2]), "r"(a[3]), "r"(b[0]), "r"(b[1]));
}
__device__ __forceinline__ void ldsm_x4(uint32_t* r, uint32_t addr) {
    asm volatile("ldmatrix.sync.aligned.m8n8.x4.shared.b16 {%0,%1,%2,%3}, [%4];"
        : "=r"(r[0]), "=r"(r[1]), "=r"(r[2]), "=r"(r[3]) : "r"(addr));
}
__device__ __forceinline__ void ldsm_x4_t(uint32_t* r, uint32_t addr) {
    asm volatile("ldmatrix.sync.aligned.m8n8.x4.trans.shared.b16 {%0,%1,%2,%3}, [%4];"
        : "=r"(r[0]), "=r"(r[1]), "=r"(r[2]), "=r"(r[3]) : "r"(addr));
}
__device__ __forceinline__ void cp_async16(uint32_t dst, const void* src) {
    asm volatile("cp.async.cg.shared.global [%0], [%1], 16;" :: "r"(dst), "l"(src));
}
#define CP_COMMIT() asm volatile("cp.async.commit_group;" ::: "memory")
#define CP_WAIT1()  asm volatile("cp.async.wait_group 1;" ::: "memory")
__device__ __forceinline__ uint32_t packbf(float lo_, float hi_) {
    uint32_t r;
    asm("cvt.rn.bf16x2.f32 %0, %1, %2;" : "=r"(r) : "f"(hi_), "f"(lo_));
    return r;
}

// ---------------------------------------------------------------------------
// fp32 -> bf16 hi + lo split (x input)
// ---------------------------------------------------------------------------
__global__ void convert_split_kernel(const float* __restrict__ src,
                                     __nv_bfloat16* __restrict__ h,
                                     __nv_bfloat16* __restrict__ l, int n)
{
    int i = blockIdx.x * blockDim.x + threadIdx.x;
    if (i >= n) return;
    float v = src[i];
    __nv_bfloat16 hh = __float2bfloat16_rn(v);
    h[i] = hh;
    l[i] = __float2bfloat16_rn(v - __bfloat162float(hh));
}

__global__ void convert_splitT_kernel(const float* __restrict__ src,
                                      __nv_bfloat16* __restrict__ h,
                                      __nv_bfloat16* __restrict__ l,
                                      int K, int N)
{
    __shared__ float t[32][33];
    int nb = blockIdx.x * 32, kb = blockIdx.y * 32;
    int tx = threadIdx.x, ty = threadIdx.y;
    #pragma unroll
    for (int j = 0; j < 4; j++)
        t[ty + j * 8][tx] = src[(size_t)(kb + ty + j * 8) * N + nb + tx];
    __syncthreads();
    #pragma unroll
    for (int j = 0; j < 4; j++) {
        float v = t[tx][ty + j * 8];
        __nv_bfloat16 hh = __float2bfloat16_rn(v);
        size_t o = (size_t)(nb + ty + j * 8) * K + kb + tx;
        h[o] = hh;
        l[o] = __float2bfloat16_rn(v - __bfloat162float(hh));
    }
}

// ---------------------------------------------------------------------------
// Split-bf16 tensor-core GEMM via mma.sync.
// ROUND-9 configuration (best measured): BM=64, 2-stage, 3 CTAs/SM.
// ---------------------------------------------------------------------------
#define BM 64
#define BN 128
#define BK 32
#define ASTRIDE 40                       // bf16 per smem row (80B)
#define A_TILE (64*80)                   // 5120 B
#define B_TILE (128*80)                  // 10240 B
#define STAGE_B (2*A_TILE + 2*B_TILE)    // 30720 B
#define GEMM_SMEM (2*STAGE_B)            // 61440 B

__global__ __launch_bounds__(256, 3)
void gemm_bf16split_kernel(const __nv_bfloat16* __restrict__ Ah,
                           const __nv_bfloat16* __restrict__ Al,
                           const __nv_bfloat16* __restrict__ Bh,
                           const __nv_bfloat16* __restrict__ Bl,
                           const float* __restrict__ bias,
                           float* __restrict__ C,
                           int M, int N, int K)
{
    extern __shared__ char sm[];
    const uint32_t sbase = smem_to_u32(sm);

    const int tid  = threadIdx.x;
    const int wid  = tid >> 5;
    const int lane = tid & 31;
    const int m0 = blockIdx.y * BM, n0 = blockIdx.x * BN;
    const int wm = (wid >> 1) * 16;
    const int wn = (wid & 1) * 64;

    float acc[8][4];
    #pragma unroll
    for (int b = 0; b < 8; b++)
        #pragma unroll
        for (int c = 0; c < 4; c++) acc[b][c] = 0.f;

    const int c_row = tid >> 2;            // 0..63
    const int c_col = (tid & 3) * 8;       // bf16 col 0,8,16,24
    const uint32_t s_off  = (uint32_t)(c_row * ASTRIDE + c_col) * 2;
    const uint32_t s_off2 = s_off + (uint32_t)64 * ASTRIDE * 2;

    const __nv_bfloat16* gAh = Ah + (size_t)(m0 + c_row) * K + c_col;
    const __nv_bfloat16* gAl = Al + (size_t)(m0 + c_row) * K + c_col;
    const __nv_bfloat16* gBh = Bh + (size_t)(n0 + c_row) * K + c_col;
    const __nv_bfloat16* gBl = Bl + (size_t)(n0 + c_row) * K + c_col;
    const size_t g2 = (size_t)64 * K;

    const int niter = K / BK;

    {
        uint32_t sb = sbase;
        cp_async16(sb + s_off,                       gAh);
        cp_async16(sb + A_TILE + s_off,              gAl);
        cp_async16(sb + 2*A_TILE + s_off,            gBh);
        cp_async16(sb + 2*A_TILE + s_off2,           gBh + g2);
        cp_async16(sb + 2*A_TILE + B_TILE + s_off,   gBl);
        cp_async16(sb + 2*A_TILE + B_TILE + s_off2,  gBl + g2);
    }
    CP_COMMIT();

    const int a_row  = (lane & 15);
    const int a_colb = (lane >> 4) * 16;
    const int b_row  = (lane & 7) + ((lane >> 4) << 3);
    const int b_colb = (((lane >> 3) & 1)) * 16;

    for (int it = 0; it < niter; it++) {
        int nk = it + 1;
        if (nk < niter) {
            uint32_t sb = sbase + (nk & 1) * STAGE_B;
            int k0 = nk * BK;
            cp_async16(sb + s_off,                      gAh + k0);
            cp_async16(sb + A_TILE + s_off,             gAl + k0);
            cp_async16(sb + 2*A_TILE + s_off,           gBh + k0);
            cp_async16(sb + 2*A_TILE + s_off2,          gBh + g2 + k0);
            cp_async16(sb + 2*A_TILE + B_TILE + s_off,  gBl + k0);
            cp_async16(sb + 2*A_TILE + B_TILE + s_off2, gBl + g2 + k0);
        }
        CP_COMMIT();
        CP_WAIT1();
        __syncthreads();

        const uint32_t sb  = sbase + (it & 1) * STAGE_B;
        const uint32_t sAh = sb;
        const uint32_t sAl = sb + A_TILE;
        const uint32_t sBh = sb + 2*A_TILE;
        const uint32_t sBl = sb + 2*A_TILE + B_TILE;

        #pragma unroll
        for (int k16 = 0; k16 < 2; k16++) {
            const int kcb = k16 * 32;
            uint32_t ah[4], al[4];
            {
                uint32_t ro = (uint32_t)(wm + a_row) * 80 + kcb + a_colb;
                ldsm_x4(ah, sAh + ro);
                ldsm_x4(al, sAl + ro);
            }
            #pragma unroll
            for (int g = 0; g < 4; g++) {
                uint32_t ro = (uint32_t)(wn + g*16 + b_row) * 80 + kcb + b_colb;
                uint32_t bh[4], bl[4];
                ldsm_x4(bh, sBh + ro);
                ldsm_x4(bl, sBl + ro);
                mma_bf16(acc[g*2+0], ah, bh + 0);
                mma_bf16(acc[g*2+1], ah, bh + 2);
                mma_bf16(acc[g*2+0], ah, bl + 0);
                mma_bf16(acc[g*2+1], ah, bl + 2);
                mma_bf16(acc[g*2+0], al, bh + 0);
                mma_bf16(acc[g*2+1], al, bh + 2);
            }
        }
        __syncthreads();
    }

    {
        int r0 = m0 + wm + (lane >> 2);
        #pragma unroll
        for (int t = 0; t < 8; t++) {
            int col = n0 + wn + t*8 + (lane & 3)*2;
            float b0 = bias[col], b1 = bias[col + 1];
            float2 v0 = { acc[t][0] + b0, acc[t][1] + b1 };
            float2 v1 = { acc[t][2] + b0, acc[t][3] + b1 };
            *(float2*)(C + (size_t)r0 * N + col)       = v0;
            *(float2*)(C + (size_t)(r0 + 8) * N + col) = v1;
        }
    }
}

// ---------------------------------------------------------------------------
// RoPE + split qkv into per-head bf16 hi/lo Q,K,V buffers [head][T][80].
// ---------------------------------------------------------------------------
__global__ void rope_split_kernel(const float* __restrict__ rope)
{
    int idx = blockIdx.x * blockDim.x + threadIdx.x;
    if (idx >= T * NH * HD) return;
    int d = idx % HD;
    int n = (idx / HD) % NH;
    int t = idx / (HD * NH);

    int dr = (d < 40) ? d : d - 40;
    float ang = rope[t * 40 + dr];
    float c = cosf(ang), s = sinf(ang);

    const float* qrow = g_qkv + (size_t)t * THID + n * HD;
    float qv, kv;
    if (d < 40) {
        qv = qrow[d] * c        - qrow[d + 40] * s;
        kv = qrow[HID + d] * c  - qrow[HID + d + 40] * s;
    } else {
        qv = qrow[d - 40] * s       + qrow[d] * c;
        kv = qrow[HID + d - 40] * s + qrow[HID + d] * c;
    }
    float vv = qrow[2 * HID + d];
    int o = (n * T + t) * HD + d;
    __nv_bfloat16 h;
    h = __float2bfloat16_rn(qv); g_qh[o] = h; g_ql[o] = __float2bfloat16_rn(qv - __bfloat162float(h));
    h = __float2bfloat16_rn(kv); g_kh[o] = h; g_kl[o] = __float2bfloat16_rn(kv - __bfloat162float(h));
    h = __float2bfloat16_rn(vv); g_vh[o] = h; g_vl[o] = __float2bfloat16_rn(vv - __bfloat162float(h));
}

// ---------------------------------------------------------------------------
// Tensor-core flash attention, block-diagonal masking.
// Round 11: 128 Q rows / 8 warps per CTA. Each KV tile load now feeds 2x the
// MMA work (KV global traffic + smem stores halved; CTAs 512 -> 256).
// Q hi (22528B) fills stage0, Q lo fills stage1 transiently in the prologue.
// ---------------------------------------------------------------------------
#define KVSB 176            // 88 bf16 row stride, conflict-free for ldmatrix
#define STG  22528
#define AQROWS 128
#define ATHREADS 256

__device__ __forceinline__ void attn_prefetch(char* sm_, int sbuf, int n, int kb,
                                              const int* __restrict__ seg,
                                              int tid, int* segk)
{
    char* dst = sm_ + sbuf * STG;
    #pragma unroll
    for (int i = 0; i < 5; i++) {
        int c = tid + i * ATHREADS;        // 0..1279
        int arr = c / 320, w = c % 320;
        int key = w / 10, cb = (w % 10) * 16;
        int kg = kb + key;
        uint4 v = make_uint4(0u, 0u, 0u, 0u);
        const __nv_bfloat16* base = (arr == 0) ? g_kh : (arr == 1) ? g_kl
                                  : (arr == 2) ? g_vh : g_vl;
        if (kg < T)
            v = *(const uint4*)((const char*)(base + (size_t)(n * T + kg) * HD) + cb);
        *(uint4*)(dst + arr * 5632 + key * KVSB + cb) = v;
    }
    if (tid < 32) segk[sbuf * 32 + tid] = (kb + tid < T) ? seg[kb + tid] : -1;
}

__global__ __launch_bounds__(ATHREADS)
void attn_mma_kernel(const int* __restrict__ seg)
{
    __shared__ __align__(16) char sm_[2 * STG + 256];
    int* segk = (int*)(sm_ + 2 * STG);
    const uint32_t sb0 = smem_to_u32(sm_);

    const int n = blockIdx.y;
    const int q0 = blockIdx.x * AQROWS;
    const int tid = threadIdx.x;
    const int lane = tid & 31;
    const int wid = tid >> 5;          // 0..7
    const int wr = wid * 16;           // warp's 16 Q rows within the 128

    const int seg_lo = seg[q0], seg_hi = seg[q0 + AQROWS - 1];
    int lo = 0, hi = T;
    while (lo < hi) { int mid = (lo + hi) >> 1; if (seg[mid] < seg_lo) lo = mid + 1; else hi = mid; }
    const int kstart = lo;
    hi = T;
    while (lo < hi) { int mid = (lo + hi) >> 1; if (seg[mid] <= seg_hi) lo = mid + 1; else hi = mid; }
    const int kend = lo;
    const int kb0 = kstart & ~31;
    const int n_tiles = (kend - kb0 + 31) >> 5;

    const int myseg0 = seg[q0 + wr + (lane >> 2)];
    const int myseg1 = seg[q0 + wr + (lane >> 2) + 8];

    // ---- prologue: Q hi -> stage0 region, Q lo -> stage1 region (transient)
    {
        const char* gq_h = (const char*)(g_qh + (size_t)(n * T + q0) * HD);
        const char* gq_l = (const char*)(g_ql + (size_t)(n * T + q0) * HD);
        #pragma unroll
        for (int i = 0; i < 5; i++) {
            int c = tid + i * ATHREADS;        // 0..1279 (128 rows x 10 chunks)
            int row = c / 10, cb = (c % 10) * 16;
            *(uint4*)(sm_ + row * KVSB + cb)       = *(const uint4*)(gq_h + row * 160 + cb);
            *(uint4*)(sm_ + STG + row * KVSB + cb) = *(const uint4*)(gq_l + row * 160 + cb);
        }
    }
    __syncthreads();

    // Q A-fragments for all 5 k16 steps (hi and lo), kept in registers.
    uint32_t qfh[5][4], qfl[5][4];
    {
        uint32_t base_h = sb0 + (uint32_t)(wr + (lane & 15)) * KVSB + ((lane >> 4) * 8) * 2;
        uint32_t base_l = base_h + STG;
        #pragma unroll
        for (int ks = 0; ks < 5; ks++) {
            ldsm_x4(qfh[ks], base_h + ks * 32);
            ldsm_x4(qfl[ks], base_l + ks * 32);
        }
    }
    __syncthreads();   // Q regions now free for KV stages

    attn_prefetch(sm_, 0, n, kb0, seg, tid, segk);
    __syncthreads();

    float OC[10][4];
    #pragma unroll
    for (int i = 0; i < 10; i++) { OC[i][0] = OC[i][1] = OC[i][2] = OC[i][3] = 0.f; }
    float m0 = -1e30f, m1 = -1e30f, l0 = 0.f, l1 = 0.f;
    const float scale = 0.11180339887498949f;   // 1/sqrt(80)

    for (int t = 0; t < n_tiles; t++) {
        if (t + 1 < n_tiles) attn_prefetch(sm_, (t + 1) & 1, n, kb0 + (t + 1) * 32, seg, tid, segk);
        const uint32_t sb = sb0 + (t & 1) * STG;
        const int* sgk = segk + (t & 1) * 32;

        // ---- S = Q K^T (3-term split), 4 n8-groups of keys
        float SC[4][4];
        #pragma unroll
        for (int g = 0; g < 4; g++) SC[g][0] = SC[g][1] = SC[g][2] = SC[g][3] = 0.f;

        const int krow = ((lane & 16) >> 1) + (lane & 7);
        #pragma unroll
        for (int ks = 0; ks < 5; ks++) {
            const int dimb = (ks * 16 + ((lane >> 3) & 1) * 8) * 2;
            #pragma unroll
            for (int gp = 0; gp < 2; gp++) {
                uint32_t kh[4], kl[4];
                uint32_t a = sb + (uint32_t)(16 * gp + krow) * KVSB + dimb;
                ldsm_x4(kh, a);
                ldsm_x4(kl, a + 5632);
                #pragma unroll
                for (int h = 0; h < 2; h++) {
                    int g = 2 * gp + h;
                    mma_bf16(SC[g], qfh[ks], kh + 2 * h);
                    mma_bf16(SC[g], qfh[ks], kl + 2 * h);
                    mma_bf16(SC[g], qfl[ks], kh + 2 * h);
                }
            }
        }

        // ---- mask + online softmax
        float sM[4][4];
        #pragma unroll
        for (int g = 0; g < 4; g++) {
            int k0i = 8 * g + 2 * (lane & 3);
            int sA = sgk[k0i], sB = sgk[k0i + 1];
            sM[g][0] = (sA == myseg0) ? SC[g][0] * scale : -1e30f;
            sM[g][1] = (sB == myseg0) ? SC[g][1] * scale : -1e30f;
            sM[g][2] = (sA == myseg1) ? SC[g][2] * scale : -1e30f;
            sM[g][3] = (sB == myseg1) ? SC[g][3] * scale : -1e30f;
        }
        float cm0 = -1e30f, cm1 = -1e30f;
        #pragma unroll
        for (int g = 0; g < 4; g++) {
            cm0 = fmaxf(cm0, fmaxf(sM[g][0], sM[g][1]));
            cm1 = fmaxf(cm1, fmaxf(sM[g][2], sM[g][3]));
        }
        cm0 = fmaxf(cm0, __shfl_xor_sync(0xffffffffu, cm0, 1));
        cm0 = fmaxf(cm0, __shfl_xor_sync(0xffffffffu, cm0, 2));
        cm1 = fmaxf(cm1, __shfl_xor_sync(0xffffffffu, cm1, 1));
        cm1 = fmaxf(cm1, __shfl_xor_sync(0xffffffffu, cm1, 2));
        float nm0 = fmaxf(m0, cm0), nm1 = fmaxf(m1, cm1);
        float f0 = __expf(m0 - nm0), f1 = __expf(m1 - nm1);
        m0 = nm0; m1 = nm1;
        l0 *= f0; l1 *= f1;
        #pragma unroll
        for (int i = 0; i < 10; i++) {
            OC[i][0] *= f0; OC[i][1] *= f0; OC[i][2] *= f1; OC[i][3] *= f1;
        }

        float p[4][4];
        #pragma unroll
        for (int g = 0; g < 4; g++) {
            p[g][0] = __expf(sM[g][0] - m0); p[g][1] = __expf(sM[g][1] - m0);
            p[g][2] = __expf(sM[g][2] - m1); p[g][3] = __expf(sM[g][3] - m1);
            l0 += p[g][0] + p[g][1];
            l1 += p[g][2] + p[g][3];
        }

        // ---- pack P -> bf16 hi/lo A-fragments
        uint32_t pah[2][4], pal[2][4];
        #pragma unroll
        for (int ks2 = 0; ks2 < 2; ks2++) {
            #pragma unroll
            for (int pos = 0; pos < 4; pos++) {
                int g = 2 * ks2 + (pos >> 1);
                int e = (pos & 1) * 2;
                float x0 = p[g][e], x1 = p[g][e + 1];
                float h0 = __bfloat162float(__float2bfloat16_rn(x0));
                float h1 = __bfloat162float(__float2bfloat16_rn(x1));
                pah[ks2][pos] = packbf(h0, h1);
                pal[ks2][pos] = packbf(x0 - h0, x1 - h1);
            }
        }

        // ---- O += P V (3-term split)
        #pragma unroll
        for (int ks2 = 0; ks2 < 2; ks2++) {
            const int vkey = 16 * ks2 + (lane & 15);
            const int vhalf = ((lane >> 4) & 1) * 16;
            #pragma unroll
            for (int dp = 0; dp < 5; dp++) {
                uint32_t vh[4], vl[4];
                uint32_t a = sb + 11264 + (uint32_t)vkey * KVSB + dp * 32 + vhalf;
                ldsm_x4_t(vh, a);
                ldsm_x4_t(vl, a + 5632);
                mma_bf16(OC[2*dp],     pah[ks2], vh + 0);
                mma_bf16(OC[2*dp],     pah[ks2], vl + 0);
                mma_bf16(OC[2*dp],     pal[ks2], vh + 0);
                mma_bf16(OC[2*dp + 1], pah[ks2], vh + 2);
                mma_bf16(OC[2*dp + 1], pah[ks2], vl + 2);
                mma_bf16(OC[2*dp + 1], pal[ks2], vh + 2);
            }
        }
        __syncthreads();
    }

    // ---- epilogue: normalize, split to bf16 hi/lo att output
    l0 += __shfl_xor_sync(0xffffffffu, l0, 1);
    l0 += __shfl_xor_sync(0xffffffffu, l0, 2);
    l1 += __shfl_xor_sync(0xffffffffu, l1, 1);
    l1 += __shfl_xor_sync(0xffffffffu, l1, 2);
    float inv0 = 1.f / l0, inv1 = 1.f / l1;
    const int row0 = q0 + wr + (lane >> 2);
    const int colb = n * HD + 2 * (lane & 3);
    #pragma unroll
    for (int ng = 0; ng < 10; ng++) {
        int col = colb + 8 * ng;
        float v0 = OC[ng][0] * inv0, v1 = OC[ng][1] * inv0;
        float v2 = OC[ng][2] * inv1, v3 = OC[ng][3] * inv1;
        float h0 = __bfloat162float(__float2bfloat16_rn(v0));
        float h1 = __bfloat162float(__float2bfloat16_rn(v1));
        float h2 = __bfloat162float(__float2bfloat16_rn(v2));
        float h3 = __bfloat162float(__float2bfloat16_rn(v3));
        *(uint32_t*)(g_ah + (size_t)row0 * HID + col)       = packbf(h0, h1);
        *(uint32_t*)(g_al + (size_t)row0 * HID + col)       = packbf(v0 - h0, v1 - h1);
        *(uint32_t*)(g_ah + (size_t)(row0 + 8) * HID + col) = packbf(h2, h3);
        *(uint32_t*)(g_al + (size_t)(row0 + 8) * HID + col) = packbf(v2 - h2, v3 - h3);
    }
}

// ---------------------------------------------------------------------------
extern "C" void kernel_launch(void* const* d_in, const int* in_sizes, int n_in,
                              void* d_out, int out_size)
{
    const float* x     = (const float*)d_in[0];
    const float* rope  = (const float*)d_in[1];
    const int*   seg   = (const int*)  d_in[2];
    const float* qkvW  = (const float*)d_in[3];
    const float* qkvB  = (const float*)d_in[4];
    const float* projW = (const float*)d_in[5];
    const float* projB = (const float*)d_in[6];
    float* out = (float*)d_out;

    float* p_qkv;
    cudaGetSymbolAddress((void**)&p_qkv, g_qkv);
    __nv_bfloat16 *p_xh, *p_xl, *p_wqh, *p_wql, *p_wph, *p_wpl, *p_ah, *p_al;
    cudaGetSymbolAddress((void**)&p_xh, g_xh);   cudaGetSymbolAddress((void**)&p_xl, g_xl);
    cudaGetSymbolAddress((void**)&p_wqh, g_wqh); cudaGetSymbolAddress((void**)&p_wql, g_wql);
    cudaGetSymbolAddress((void**)&p_wph, g_wph); cudaGetSymbolAddress((void**)&p_wpl, g_wpl);
    cudaGetSymbolAddress((void**)&p_ah, g_ah);   cudaGetSymbolAddress((void**)&p_al, g_al);

    cudaFuncSetAttribute(gemm_bf16split_kernel,
                         cudaFuncAttributeMaxDynamicSharedMemorySize, GEMM_SMEM);

    // 0. convert inputs to split-bf16 (weights transposed to [N][K])
    convert_split_kernel<<<(T*HID + 255)/256, 256>>>(x, p_xh, p_xl, T*HID);
    convert_splitT_kernel<<<dim3(THID/32, HID/32), dim3(32, 8)>>>(qkvW, p_wqh, p_wql, HID, THID);
    convert_splitT_kernel<<<dim3(HID/32, HID/32), dim3(32, 8)>>>(projW, p_wph, p_wpl, HID, HID);

    // 1. qkv = x @ Wqkv + b   (mma.sync split-bf16, round-9 config)
    gemm_bf16split_kernel<<<dim3(THID/BN, T/BM), 256, GEMM_SMEM>>>(
        p_xh, p_xl, p_wqh, p_wql, qkvB, p_qkv, T, THID, HID);

    // 2. RoPE + split into per-head bf16 hi/lo Q,K,V
    rope_split_kernel<<<(T*NH*HD + 255)/256, 256>>>(rope);

    // 3. Tensor-core block-diagonal flash attention (128 Q rows / CTA)
    attn_mma_kernel<<<dim3(T/AQROWS, NH), ATHREADS>>>(seg);

    // 4. out = att @ Wproj + b
    gemm_bf16split_kernel<<<dim3(HID/BN, T/BM), 256, GEMM_SMEM>>>(
        p_ah, p_al, p_wph, p_wpl, projB, out, T, HID, HID);
}

// round 12
// speedup vs baseline: 1.3701x; 1.3549x over previous
#include <cuda_runtime.h>
#include <cuda_bf16.h>
#include <cuda_fp16.h>
#include <cstdint>
#include <math.h>

#define T 2048
#define HID 1280
#define NH 16
#define HD 80
#define THID (3*HID)

// ---------------- scratch (static device allocations only) ----------------
__device__ float g_qkv[T*THID];

// fp16 operands for dense GEMMs (A split hi/lo, B single)
__device__ __half g_xh[T*HID],  g_xl[T*HID];
__device__ __half g_wq[THID*HID];          // Wqkv^T [3840][1280] fp16
__device__ __half g_wp[HID*HID];           // Wproj^T [1280][1280] fp16
__device__ __half g_ah[T*HID],  g_al[T*HID];

// bf16 hi/lo roped Q,K and V, per head: [head][T][80] (attention stays bf16 3-term)
__device__ __nv_bfloat16 g_qh[NH*T*HD], g_ql[NH*T*HD];
__device__ __nv_bfloat16 g_kh[NH*T*HD], g_kl[NH*T*HD];
__device__ __nv_bfloat16 g_vh[NH*T*HD], g_vl[NH*T*HD];

// ---------------- helpers ----------------
__device__ __forceinline__ uint32_t smem_to_u32(const void* p) {
    uint32_t a;
    asm("{ .reg .u64 tmp; cvta.to.shared.u64 tmp, %1; cvt.u32.u64 %0, tmp; }"
        : "=r"(a) : "l"(p));
    return a;
}
__device__ __forceinline__ void mma_bf16(float* c, const uint32_t* a, const uint32_t* b) {
    asm volatile("mma.sync.aligned.m16n8k16.row.col.f32.bf16.bf16.f32 "
        "{%0,%1,%2,%3}, {%4,%5,%6,%7}, {%8,%9}, {%0,%1,%2,%3};"
        : "+f"(c[0]), "+f"(c[1]), "+f"(c[2]), "+f"(c[3])
        : "r"(a[0]), "r"(a[1]), "r"(a[2]), "r"(a[3]), "r"(b[0]), "r"(b[1]));
}
__device__ __forceinline__ void mma_f16(float* c, const uint32_t* a, const uint32_t* b) {
    asm volatile("mma.sync.aligned.m16n8k16.row.col.f32.f16.f16.f32 "
        "{%0,%1,%2,%3}, {%4,%5,%6,%7}, {%8,%9}, {%0,%1,%2,%3};"
        : "+f"(c[0]), "+f"(c[1]), "+f"(c[2]), "+f"(c[3])
        : "r"(a[0]), "r"(a[1]), "r"(a[2]), "r"(a[3]), "r"(b[0]), "r"(b[1]));
}
__device__ __forceinline__ void ldsm_x4(uint32_t* r, uint32_t addr) {
    asm volatile("ldmatrix.sync.aligned.m8n8.x4.shared.b16 {%0,%1,%2,%3}, [%4];"
        : "=r"(r[0]), "=r"(r[1]), "=r"(r[2]), "=r"(r[3]) : "r"(addr));
}
__device__ __forceinline__ void ldsm_x4_t(uint32_t* r, uint32_t addr) {
    asm volatile("ldmatrix.sync.aligned.m8n8.x4.trans.shared.b16 {%0,%1,%2,%3}, [%4];"
        : "=r"(r[0]), "=r"(r[1]), "=r"(r[2]), "=r"(r[3]) : "r"(addr));
}
__device__ __forceinline__ void cp_async16(uint32_t dst, const void* src) {
    asm volatile("cp.async.cg.shared.global [%0], [%1], 16;" :: "r"(dst), "l"(src));
}
#define CP_COMMIT() asm volatile("cp.async.commit_group;" ::: "memory")
#define CP_WAIT1()  asm volatile("cp.async.wait_group 1;" ::: "memory")
__device__ __forceinline__ uint32_t packbf(float lo_, float hi_) {
    uint32_t r;
    asm("cvt.rn.bf16x2.f32 %0, %1, %2;" : "=r"(r) : "f"(hi_), "f"(lo_));
    return r;
}

// ---------------------------------------------------------------------------
// fp32 -> fp16 hi + fp16 lo split (GEMM A operands)
// ---------------------------------------------------------------------------
__global__ void convert_splitA_kernel(const float* __restrict__ src,
                                      __half* __restrict__ h,
                                      __half* __restrict__ l, int n)
{
    int i = blockIdx.x * blockDim.x + threadIdx.x;
    if (i >= n) return;
    float v = src[i];
    __half hh = __float2half_rn(v);
    h[i] = hh;
    l[i] = __float2half_rn(v - __half2float(hh));
}

// Transpose [K][N] -> [N][K], single fp16 (GEMM B operand)
__global__ void convertT_kernel(const float* __restrict__ src,
                                __half* __restrict__ h,
                                int K, int N)
{
    __shared__ float t[32][33];
    int nb = blockIdx.x * 32, kb = blockIdx.y * 32;
    int tx = threadIdx.x, ty = threadIdx.y;   // (32, 8)
    #pragma unroll
    for (int j = 0; j < 4; j++)
        t[ty + j * 8][tx] = src[(size_t)(kb + ty + j * 8) * N + nb + tx];
    __syncthreads();
    #pragma unroll
    for (int j = 0; j < 4; j++)
        h[(size_t)(nb + ty + j * 8) * K + kb + tx] = __float2half_rn(t[tx][ty + j * 8]);
}

// ---------------------------------------------------------------------------
// fp16 asymmetric 2-term tensor-core GEMM: C = (Ah+Al)[M,K] @ Bh[N,K]^T + bias
// Round-9 pipeline config (BM=64, 2-stage, 3 CTA/SM); 4 MMAs per g-group.
// ---------------------------------------------------------------------------
#define BM 64
#define BN 128
#define BK 32
#define ASTRIDE 40                       // fp16 per smem row (80B stride, 64B data)
#define A_TILE (64*80)                   // 5120 B
#define B_TILE (128*80)                  // 10240 B
#define STAGE_B (2*A_TILE + B_TILE)      // 20480 B
#define GEMM_SMEM (2*STAGE_B)            // 40960 B

__global__ __launch_bounds__(256, 3)
void gemm_f16split_kernel(const __half* __restrict__ Ah,
                          const __half* __restrict__ Al,
                          const __half* __restrict__ Bh,
                          const float* __restrict__ bias,
                          float* __restrict__ C,
                          int M, int N, int K)
{
    extern __shared__ char sm[];
    const uint32_t sbase = smem_to_u32(sm);

    const int tid  = threadIdx.x;
    const int wid  = tid >> 5;
    const int lane = tid & 31;
    const int m0 = blockIdx.y * BM, n0 = blockIdx.x * BN;
    const int wm = (wid >> 1) * 16;
    const int wn = (wid & 1) * 64;

    float acc[8][4];
    #pragma unroll
    for (int b = 0; b < 8; b++)
        #pragma unroll
        for (int c = 0; c < 4; c++) acc[b][c] = 0.f;

    const int c_row = tid >> 2;            // 0..63
    const int c_col = (tid & 3) * 8;       // fp16 col 0,8,16,24
    const uint32_t s_off  = (uint32_t)(c_row * ASTRIDE + c_col) * 2;
    const uint32_t s_off2 = s_off + (uint32_t)64 * ASTRIDE * 2;

    const __half* gAh = Ah + (size_t)(m0 + c_row) * K + c_col;
    const __half* gAl = Al + (size_t)(m0 + c_row) * K + c_col;
    const __half* gBh = Bh + (size_t)(n0 + c_row) * K + c_col;
    const size_t g2 = (size_t)64 * K;

    const int niter = K / BK;

    {
        uint32_t sb = sbase;
        cp_async16(sb + s_off,              gAh);
        cp_async16(sb + A_TILE + s_off,     gAl);
        cp_async16(sb + 2*A_TILE + s_off,   gBh);
        cp_async16(sb + 2*A_TILE + s_off2,  gBh + g2);
    }
    CP_COMMIT();

    const int a_row  = (lane & 15);
    const int a_colb = (lane >> 4) * 16;
    const int b_row  = (lane & 7) + ((lane >> 4) << 3);
    const int b_colb = (((lane >> 3) & 1)) * 16;

    for (int it = 0; it < niter; it++) {
        int nk = it + 1;
        if (nk < niter) {
            uint32_t sb = sbase + (nk & 1) * STAGE_B;
            int k0 = nk * BK;
            cp_async16(sb + s_off,              gAh + k0);
            cp_async16(sb + A_TILE + s_off,     gAl + k0);
            cp_async16(sb + 2*A_TILE + s_off,   gBh + k0);
            cp_async16(sb + 2*A_TILE + s_off2,  gBh + g2 + k0);
        }
        CP_COMMIT();
        CP_WAIT1();
        __syncthreads();

        const uint32_t sb  = sbase + (it & 1) * STAGE_B;
        const uint32_t sAh = sb;
        const uint32_t sAl = sb + A_TILE;
        const uint32_t sBh = sb + 2*A_TILE;

        #pragma unroll
        for (int k16 = 0; k16 < 2; k16++) {
            const int kcb = k16 * 32;
            uint32_t ah[4], al[4];
            {
                uint32_t ro = (uint32_t)(wm + a_row) * 80 + kcb + a_colb;
                ldsm_x4(ah, sAh + ro);
                ldsm_x4(al, sAl + ro);
            }
            #pragma unroll
            for (int g = 0; g < 4; g++) {
                uint32_t ro = (uint32_t)(wn + g*16 + b_row) * 80 + kcb + b_colb;
                uint32_t bh[4];
                ldsm_x4(bh, sBh + ro);
                mma_f16(acc[g*2+0], ah, bh + 0);
                mma_f16(acc[g*2+1], ah, bh + 2);
                mma_f16(acc[g*2+0], al, bh + 0);
                mma_f16(acc[g*2+1], al, bh + 2);
            }
        }
        __syncthreads();
    }

    {
        int r0 = m0 + wm + (lane >> 2);
        #pragma unroll
        for (int t = 0; t < 8; t++) {
            int col = n0 + wn + t*8 + (lane & 3)*2;
            float b0 = bias[col], b1 = bias[col + 1];
            float2 v0 = { acc[t][0] + b0, acc[t][1] + b1 };
            float2 v1 = { acc[t][2] + b0, acc[t][3] + b1 };
            *(float2*)(C + (size_t)r0 * N + col)       = v0;
            *(float2*)(C + (size_t)(r0 + 8) * N + col) = v1;
        }
    }
}

// ---------------------------------------------------------------------------
// RoPE + split qkv into per-head bf16 hi/lo Q,K,V buffers [head][T][80].
// ---------------------------------------------------------------------------
__global__ void rope_split_kernel(const float* __restrict__ rope)
{
    int idx = blockIdx.x * blockDim.x + threadIdx.x;
    if (idx >= T * NH * HD) return;
    int d = idx % HD;
    int n = (idx / HD) % NH;
    int t = idx / (HD * NH);

    int dr = (d < 40) ? d : d - 40;
    float ang = rope[t * 40 + dr];
    float c = cosf(ang), s = sinf(ang);

    const float* qrow = g_qkv + (size_t)t * THID + n * HD;
    float qv, kv;
    if (d < 40) {
        qv = qrow[d] * c        - qrow[d + 40] * s;
        kv = qrow[HID + d] * c  - qrow[HID + d + 40] * s;
    } else {
        qv = qrow[d - 40] * s       + qrow[d] * c;
        kv = qrow[HID + d - 40] * s + qrow[HID + d] * c;
    }
    float vv = qrow[2 * HID + d];
    int o = (n * T + t) * HD + d;
    __nv_bfloat16 h;
    h = __float2bfloat16_rn(qv); g_qh[o] = h; g_ql[o] = __float2bfloat16_rn(qv - __bfloat162float(h));
    h = __float2bfloat16_rn(kv); g_kh[o] = h; g_kl[o] = __float2bfloat16_rn(kv - __bfloat162float(h));
    h = __float2bfloat16_rn(vv); g_vh[o] = h; g_vl[o] = __float2bfloat16_rn(vv - __bfloat162float(h));
}

// ---------------------------------------------------------------------------
// Tensor-core flash attention with block-diagonal masking (round-9 version,
// 64 Q rows / 128 threads). Epilogue emits fp16 hi/lo for the proj GEMM.
// ---------------------------------------------------------------------------
#define KVSB 176
#define STG  22528

__device__ __forceinline__ void attn_prefetch(char* sm_, int sbuf, int n, int kb,
                                              const int* __restrict__ seg,
                                              int tid, int* segk)
{
    char* dst = sm_ + sbuf * STG;
    #pragma unroll
    for (int i = 0; i < 10; i++) {
        int c = tid + i * 128;
        int arr = c / 320, w = c % 320;
        int key = w / 10, cb = (w % 10) * 16;
        int kg = kb + key;
        uint4 v = make_uint4(0u, 0u, 0u, 0u);
        const __nv_bfloat16* base = (arr == 0) ? g_kh : (arr == 1) ? g_kl
                                  : (arr == 2) ? g_vh : g_vl;
        if (kg < T)
            v = *(const uint4*)((const char*)(base + (size_t)(n * T + kg) * HD) + cb);
        *(uint4*)(dst + arr * 5632 + key * KVSB + cb) = v;
    }
    if (tid < 32) segk[sbuf * 32 + tid] = (kb + tid < T) ? seg[kb + tid] : -1;
}

__global__ __launch_bounds__(128)
void attn_mma_kernel(const int* __restrict__ seg)
{
    __shared__ __align__(16) char sm_[2 * STG + 256];
    int* segk = (int*)(sm_ + 2 * STG);
    const uint32_t sb0 = smem_to_u32(sm_);

    const int n = blockIdx.y;
    const int q0 = blockIdx.x * 64;
    const int tid = threadIdx.x;
    const int lane = tid & 31;
    const int wid = tid >> 5;
    const int wr = wid * 16;

    const int seg_lo = seg[q0], seg_hi = seg[q0 + 63];
    int lo = 0, hi = T;
    while (lo < hi) { int mid = (lo + hi) >> 1; if (seg[mid] < seg_lo) lo = mid + 1; else hi = mid; }
    const int kstart = lo;
    hi = T;
    while (lo < hi) { int mid = (lo + hi) >> 1; if (seg[mid] <= seg_hi) lo = mid + 1; else hi = mid; }
    const int kend = lo;
    const int kb0 = kstart & ~31;
    const int n_tiles = (kend - kb0 + 31) >> 5;

    const int myseg0 = seg[q0 + wr + (lane >> 2)];
    const int myseg1 = seg[q0 + wr + (lane >> 2) + 8];

    {
        const char* gq_h = (const char*)(g_qh + (size_t)(n * T + q0) * HD);
        const char* gq_l = (const char*)(g_ql + (size_t)(n * T + q0) * HD);
        #pragma unroll
        for (int i = 0; i < 5; i++) {
            int c = tid + i * 128;
            int row = c / 10, cb = (c % 10) * 16;
            *(uint4*)(sm_ + STG + row * KVSB + cb)         = *(const uint4*)(gq_h + row * 160 + cb);
            *(uint4*)(sm_ + STG + 11264 + row * KVSB + cb) = *(const uint4*)(gq_l + row * 160 + cb);
        }
    }
    attn_prefetch(sm_, 0, n, kb0, seg, tid, segk);
    __syncthreads();

    uint32_t qfh[5][4], qfl[5][4];
    {
        uint32_t base_h = sb0 + STG + (uint32_t)(wr + (lane & 15)) * KVSB + ((lane >> 4) * 8) * 2;
        uint32_t base_l = base_h + 11264;
        #pragma unroll
        for (int ks = 0; ks < 5; ks++) {
            ldsm_x4(qfh[ks], base_h + ks * 32);
            ldsm_x4(qfl[ks], base_l + ks * 32);
        }
    }
    __syncthreads();

    float OC[10][4];
    #pragma unroll
    for (int i = 0; i < 10; i++) { OC[i][0] = OC[i][1] = OC[i][2] = OC[i][3] = 0.f; }
    float m0 = -1e30f, m1 = -1e30f, l0 = 0.f, l1 = 0.f;
    const float scale = 0.11180339887498949f;

    for (int t = 0; t < n_tiles; t++) {
        if (t + 1 < n_tiles) attn_prefetch(sm_, (t + 1) & 1, n, kb0 + (t + 1) * 32, seg, tid, segk);
        const uint32_t sb = sb0 + (t & 1) * STG;
        const int* sgk = segk + (t & 1) * 32;

        float SC[4][4];
        #pragma unroll
        for (int g = 0; g < 4; g++) SC[g][0] = SC[g][1] = SC[g][2] = SC[g][3] = 0.f;

        const int krow = ((lane & 16) >> 1) + (lane & 7);
        #pragma unroll
        for (int ks = 0; ks < 5; ks++) {
            const int dimb = (ks * 16 + ((lane >> 3) & 1) * 8) * 2;
            #pragma unroll
            for (int gp = 0; gp < 2; gp++) {
                uint32_t kh[4], kl[4];
                uint32_t a = sb + (uint32_t)(16 * gp + krow) * KVSB + dimb;
                ldsm_x4(kh, a);
                ldsm_x4(kl, a + 5632);
                #pragma unroll
                for (int h = 0; h < 2; h++) {
                    int g = 2 * gp + h;
                    mma_bf16(SC[g], qfh[ks], kh + 2 * h);
                    mma_bf16(SC[g], qfh[ks], kl + 2 * h);
                    mma_bf16(SC[g], qfl[ks], kh + 2 * h);
                }
            }
        }

        float sM[4][4];
        #pragma unroll
        for (int g = 0; g < 4; g++) {
            int k0i = 8 * g + 2 * (lane & 3);
            int sA = sgk[k0i], sB = sgk[k0i + 1];
            sM[g][0] = (sA == myseg0) ? SC[g][0] * scale : -1e30f;
            sM[g][1] = (sB == myseg0) ? SC[g][1] * scale : -1e30f;
            sM[g][2] = (sA == myseg1) ? SC[g][2] * scale : -1e30f;
            sM[g][3] = (sB == myseg1) ? SC[g][3] * scale : -1e30f;
        }
        float cm0 = -1e30f, cm1 = -1e30f;
        #pragma unroll
        for (int g = 0; g < 4; g++) {
            cm0 = fmaxf(cm0, fmaxf(sM[g][0], sM[g][1]));
            cm1 = fmaxf(cm1, fmaxf(sM[g][2], sM[g][3]));
        }
        cm0 = fmaxf(cm0, __shfl_xor_sync(0xffffffffu, cm0, 1));
        cm0 = fmaxf(cm0, __shfl_xor_sync(0xffffffffu, cm0, 2));
        cm1 = fmaxf(cm1, __shfl_xor_sync(0xffffffffu, cm1, 1));
        cm1 = fmaxf(cm1, __shfl_xor_sync(0xffffffffu, cm1, 2));
        float nm0 = fmaxf(m0, cm0), nm1 = fmaxf(m1, cm1);
        float f0 = __expf(m0 - nm0), f1 = __expf(m1 - nm1);
        m0 = nm0; m1 = nm1;
        l0 *= f0; l1 *= f1;
        #pragma unroll
        for (int i = 0; i < 10; i++) {
            OC[i][0] *= f0; OC[i][1] *= f0; OC[i][2] *= f1; OC[i][3] *= f1;
        }

        float p[4][4];
        #pragma unroll
        for (int g = 0; g < 4; g++) {
            p[g][0] = __expf(sM[g][0] - m0); p[g][1] = __expf(sM[g][1] - m0);
            p[g][2] = __expf(sM[g][2] - m1); p[g][3] = __expf(sM[g][3] - m1);
            l0 += p[g][0] + p[g][1];
            l1 += p[g][2] + p[g][3];
        }

        uint32_t pah[2][4], pal[2][4];
        #pragma unroll
        for (int ks2 = 0; ks2 < 2; ks2++) {
            #pragma unroll
            for (int pos = 0; pos < 4; pos++) {
                int g = 2 * ks2 + (pos >> 1);
                int e = (pos & 1) * 2;
                float x0 = p[g][e], x1 = p[g][e + 1];
                float h0 = __bfloat162float(__float2bfloat16_rn(x0));
                float h1 = __bfloat162float(__float2bfloat16_rn(x1));
                pah[ks2][pos] = packbf(h0, h1);
                pal[ks2][pos] = packbf(x0 - h0, x1 - h1);
            }
        }

        #pragma unroll
        for (int ks2 = 0; ks2 < 2; ks2++) {
            const int vkey = 16 * ks2 + (lane & 15);
            const int vhalf = ((lane >> 4) & 1) * 16;
            #pragma unroll
            for (int dp = 0; dp < 5; dp++) {
                uint32_t vh[4], vl[4];
                uint32_t a = sb + 11264 + (uint32_t)vkey * KVSB + dp * 32 + vhalf;
                ldsm_x4_t(vh, a);
                ldsm_x4_t(vl, a + 5632);
                mma_bf16(OC[2*dp],     pah[ks2], vh + 0);
                mma_bf16(OC[2*dp],     pah[ks2], vl + 0);
                mma_bf16(OC[2*dp],     pal[ks2], vh + 0);
                mma_bf16(OC[2*dp + 1], pah[ks2], vh + 2);
                mma_bf16(OC[2*dp + 1], pah[ks2], vl + 2);
                mma_bf16(OC[2*dp + 1], pal[ks2], vh + 2);
            }
        }
        __syncthreads();
    }

    l0 += __shfl_xor_sync(0xffffffffu, l0, 1);
    l0 += __shfl_xor_sync(0xffffffffu, l0, 2);
    l1 += __shfl_xor_sync(0xffffffffu, l1, 1);
    l1 += __shfl_xor_sync(0xffffffffu, l1, 2);
    float inv0 = 1.f / l0, inv1 = 1.f / l1;
    const int row0 = q0 + wr + (lane >> 2);
    const int colb = n * HD + 2 * (lane & 3);
    #pragma unroll
    for (int ng = 0; ng < 10; ng++) {
        int col = colb + 8 * ng;
        float v0 = OC[ng][0] * inv0, v1 = OC[ng][1] * inv0;
        float v2 = OC[ng][2] * inv1, v3 = OC[ng][3] * inv1;
        // fp16 hi/lo split for the proj GEMM (A operand)
        __half h0 = __float2half_rn(v0), h1 = __float2half_rn(v1);
        __half h2 = __float2half_rn(v2), h3 = __float2half_rn(v3);
        *(__half2*)(g_ah + (size_t)row0 * HID + col) = __halves2half2(h0, h1);
        *(__half2*)(g_al + (size_t)row0 * HID + col) =
            __halves2half2(__float2half_rn(v0 - __half2float(h0)),
                           __float2half_rn(v1 - __half2float(h1)));
        *(__half2*)(g_ah + (size_t)(row0 + 8) * HID + col) = __halves2half2(h2, h3);
        *(__half2*)(g_al + (size_t)(row0 + 8) * HID + col) =
            __halves2half2(__float2half_rn(v2 - __half2float(h2)),
                           __float2half_rn(v3 - __half2float(h3)));
    }
}

// ---------------------------------------------------------------------------
extern "C" void kernel_launch(void* const* d_in, const int* in_sizes, int n_in,
                              void* d_out, int out_size)
{
    const float* x     = (const float*)d_in[0];
    const float* rope  = (const float*)d_in[1];
    const int*   seg   = (const int*)  d_in[2];
    const float* qkvW  = (const float*)d_in[3];
    const float* qkvB  = (const float*)d_in[4];
    const float* projW = (const float*)d_in[5];
    const float* projB = (const float*)d_in[6];
    float* out = (float*)d_out;

    float* p_qkv;
    cudaGetSymbolAddress((void**)&p_qkv, g_qkv);
    __half *p_xh, *p_xl, *p_wq, *p_wp, *p_ah, *p_al;
    cudaGetSymbolAddress((void**)&p_xh, g_xh); cudaGetSymbolAddress((void**)&p_xl, g_xl);
    cudaGetSymbolAddress((void**)&p_wq, g_wq); cudaGetSymbolAddress((void**)&p_wp, g_wp);
    cudaGetSymbolAddress((void**)&p_ah, g_ah); cudaGetSymbolAddress((void**)&p_al, g_al);

    cudaFuncSetAttribute(gemm_f16split_kernel,
                         cudaFuncAttributeMaxDynamicSharedMemorySize, GEMM_SMEM);

    // 0. convert inputs (A: fp16 hi/lo split; B: transposed single fp16)
    convert_splitA_kernel<<<(T*HID + 255)/256, 256>>>(x, p_xh, p_xl, T*HID);
    convertT_kernel<<<dim3(THID/32, HID/32), dim3(32, 8)>>>(qkvW, p_wq, HID, THID);
    convertT_kernel<<<dim3(HID/32, HID/32), dim3(32, 8)>>>(projW, p_wp, HID, HID);

    // 1. qkv = x @ Wqkv + b   (fp16 asymmetric 2-term)
    gemm_f16split_kernel<<<dim3(THID/BN, T/BM), 256, GEMM_SMEM>>>(
        p_xh, p_xl, p_wq, qkvB, p_qkv, T, THID, HID);

    // 2. RoPE + split into per-head bf16 hi/lo Q,K,V
    rope_split_kernel<<<(T*NH*HD + 255)/256, 256>>>(rope);

    // 3. Tensor-core block-diagonal flash attention -> fp16 hi/lo att
    attn_mma_kernel<<<dim3(T/64, NH), 128>>>(seg);

    // 4. out = att @ Wproj + b   (fp16 asymmetric 2-term)
    gemm_f16split_kernel<<<dim3(HID/BN, T/BM), 256, GEMM_SMEM>>>(
        p_ah, p_al, p_wp, projB, out, T, HID, HID);
}

// round 13
// speedup vs baseline: 1.5289x; 1.1159x over previous
#include <cuda_runtime.h>
#include <cuda_bf16.h>
#include <cuda_fp16.h>
#include <cstdint>
#include <math.h>

#define T 2048
#define HID 1280
#define NH 16
#define HD 80
#define THID (3*HID)

// ---------------- scratch (static device allocations only) ----------------
__device__ float g_qkv[T*THID];

// fp16 operands for dense GEMMs (A split hi/lo, B single)
__device__ __half g_xh[T*HID],  g_xl[T*HID];
__device__ __half g_wq[THID*HID];          // Wqkv^T [3840][1280] fp16
__device__ __half g_wp[HID*HID];           // Wproj^T [1280][1280] fp16
__device__ __half g_ah[T*HID],  g_al[T*HID];

// fp16 roped Q (hi/lo) and K,V (single), per head: [head][T][80]
__device__ __half g_q16h[NH*T*HD], g_q16l[NH*T*HD];
__device__ __half g_k16[NH*T*HD];
__device__ __half g_v16[NH*T*HD];

// ---------------- helpers ----------------
__device__ __forceinline__ uint32_t smem_to_u32(const void* p) {
    uint32_t a;
    asm("{ .reg .u64 tmp; cvta.to.shared.u64 tmp, %1; cvt.u32.u64 %0, tmp; }"
        : "=r"(a) : "l"(p));
    return a;
}
__device__ __forceinline__ void mma_f16(float* c, const uint32_t* a, const uint32_t* b) {
    asm volatile("mma.sync.aligned.m16n8k16.row.col.f32.f16.f16.f32 "
        "{%0,%1,%2,%3}, {%4,%5,%6,%7}, {%8,%9}, {%0,%1,%2,%3};"
        : "+f"(c[0]), "+f"(c[1]), "+f"(c[2]), "+f"(c[3])
        : "r"(a[0]), "r"(a[1]), "r"(a[2]), "r"(a[3]), "r"(b[0]), "r"(b[1]));
}
__device__ __forceinline__ void ldsm_x4(uint32_t* r, uint32_t addr) {
    asm volatile("ldmatrix.sync.aligned.m8n8.x4.shared.b16 {%0,%1,%2,%3}, [%4];"
        : "=r"(r[0]), "=r"(r[1]), "=r"(r[2]), "=r"(r[3]) : "r"(addr));
}
__device__ __forceinline__ void ldsm_x4_t(uint32_t* r, uint32_t addr) {
    asm volatile("ldmatrix.sync.aligned.m8n8.x4.trans.shared.b16 {%0,%1,%2,%3}, [%4];"
        : "=r"(r[0]), "=r"(r[1]), "=r"(r[2]), "=r"(r[3]) : "r"(addr));
}
__device__ __forceinline__ void cp_async16(uint32_t dst, const void* src) {
    asm volatile("cp.async.cg.shared.global [%0], [%1], 16;" :: "r"(dst), "l"(src));
}
#define CP_COMMIT() asm volatile("cp.async.commit_group;" ::: "memory")
#define CP_WAIT1()  asm volatile("cp.async.wait_group 1;" ::: "memory")
__device__ __forceinline__ uint32_t packh(float lo_, float hi_) {
    uint32_t r;
    asm("cvt.rn.f16x2.f32 %0, %1, %2;" : "=r"(r) : "f"(hi_), "f"(lo_));
    return r;
}

// ---------------------------------------------------------------------------
// fp32 -> fp16 hi + fp16 lo split (GEMM A operands)
// ---------------------------------------------------------------------------
__global__ void convert_splitA_kernel(const float* __restrict__ src,
                                      __half* __restrict__ h,
                                      __half* __restrict__ l, int n)
{
    int i = blockIdx.x * blockDim.x + threadIdx.x;
    if (i >= n) return;
    float v = src[i];
    __half hh = __float2half_rn(v);
    h[i] = hh;
    l[i] = __float2half_rn(v - __half2float(hh));
}

// Transpose [K][N] -> [N][K], single fp16 (GEMM B operand)
__global__ void convertT_kernel(const float* __restrict__ src,
                                __half* __restrict__ h,
                                int K, int N)
{
    __shared__ float t[32][33];
    int nb = blockIdx.x * 32, kb = blockIdx.y * 32;
    int tx = threadIdx.x, ty = threadIdx.y;   // (32, 8)
    #pragma unroll
    for (int j = 0; j < 4; j++)
        t[ty + j * 8][tx] = src[(size_t)(kb + ty + j * 8) * N + nb + tx];
    __syncthreads();
    #pragma unroll
    for (int j = 0; j < 4; j++)
        h[(size_t)(nb + ty + j * 8) * K + kb + tx] = __float2half_rn(t[tx][ty + j * 8]);
}

// ---------------------------------------------------------------------------
// fp16 asymmetric 2-term tensor-core GEMM (unchanged from round 12: 126us QKV)
// ---------------------------------------------------------------------------
#define BM 64
#define BN 128
#define BK 32
#define ASTRIDE 40
#define A_TILE (64*80)
#define B_TILE (128*80)
#define STAGE_B (2*A_TILE + B_TILE)      // 20480 B
#define GEMM_SMEM (2*STAGE_B)            // 40960 B

__global__ __launch_bounds__(256, 3)
void gemm_f16split_kernel(const __half* __restrict__ Ah,
                          const __half* __restrict__ Al,
                          const __half* __restrict__ Bh,
                          const float* __restrict__ bias,
                          float* __restrict__ C,
                          int M, int N, int K)
{
    extern __shared__ char sm[];
    const uint32_t sbase = smem_to_u32(sm);

    const int tid  = threadIdx.x;
    const int wid  = tid >> 5;
    const int lane = tid & 31;
    const int m0 = blockIdx.y * BM, n0 = blockIdx.x * BN;
    const int wm = (wid >> 1) * 16;
    const int wn = (wid & 1) * 64;

    float acc[8][4];
    #pragma unroll
    for (int b = 0; b < 8; b++)
        #pragma unroll
        for (int c = 0; c < 4; c++) acc[b][c] = 0.f;

    const int c_row = tid >> 2;
    const int c_col = (tid & 3) * 8;
    const uint32_t s_off  = (uint32_t)(c_row * ASTRIDE + c_col) * 2;
    const uint32_t s_off2 = s_off + (uint32_t)64 * ASTRIDE * 2;

    const __half* gAh = Ah + (size_t)(m0 + c_row) * K + c_col;
    const __half* gAl = Al + (size_t)(m0 + c_row) * K + c_col;
    const __half* gBh = Bh + (size_t)(n0 + c_row) * K + c_col;
    const size_t g2 = (size_t)64 * K;

    const int niter = K / BK;

    {
        uint32_t sb = sbase;
        cp_async16(sb + s_off,              gAh);
        cp_async16(sb + A_TILE + s_off,     gAl);
        cp_async16(sb + 2*A_TILE + s_off,   gBh);
        cp_async16(sb + 2*A_TILE + s_off2,  gBh + g2);
    }
    CP_COMMIT();

    const int a_row  = (lane & 15);
    const int a_colb = (lane >> 4) * 16;
    const int b_row  = (lane & 7) + ((lane >> 4) << 3);
    const int b_colb = (((lane >> 3) & 1)) * 16;

    for (int it = 0; it < niter; it++) {
        int nk = it + 1;
        if (nk < niter) {
            uint32_t sb = sbase + (nk & 1) * STAGE_B;
            int k0 = nk * BK;
            cp_async16(sb + s_off,              gAh + k0);
            cp_async16(sb + A_TILE + s_off,     gAl + k0);
            cp_async16(sb + 2*A_TILE + s_off,   gBh + k0);
            cp_async16(sb + 2*A_TILE + s_off2,  gBh + g2 + k0);
        }
        CP_COMMIT();
        CP_WAIT1();
        __syncthreads();

        const uint32_t sb  = sbase + (it & 1) * STAGE_B;
        const uint32_t sAh = sb;
        const uint32_t sAl = sb + A_TILE;
        const uint32_t sBh = sb + 2*A_TILE;

        #pragma unroll
        for (int k16 = 0; k16 < 2; k16++) {
            const int kcb = k16 * 32;
            uint32_t ah[4], al[4];
            {
                uint32_t ro = (uint32_t)(wm + a_row) * 80 + kcb + a_colb;
                ldsm_x4(ah, sAh + ro);
                ldsm_x4(al, sAl + ro);
            }
            #pragma unroll
            for (int g = 0; g < 4; g++) {
                uint32_t ro = (uint32_t)(wn + g*16 + b_row) * 80 + kcb + b_colb;
                uint32_t bh[4];
                ldsm_x4(bh, sBh + ro);
                mma_f16(acc[g*2+0], ah, bh + 0);
                mma_f16(acc[g*2+1], ah, bh + 2);
                mma_f16(acc[g*2+0], al, bh + 0);
                mma_f16(acc[g*2+1], al, bh + 2);
            }
        }
        __syncthreads();
    }

    {
        int r0 = m0 + wm + (lane >> 2);
        #pragma unroll
        for (int t = 0; t < 8; t++) {
            int col = n0 + wn + t*8 + (lane & 3)*2;
            float b0 = bias[col], b1 = bias[col + 1];
            float2 v0 = { acc[t][0] + b0, acc[t][1] + b1 };
            float2 v1 = { acc[t][2] + b0, acc[t][3] + b1 };
            *(float2*)(C + (size_t)r0 * N + col)       = v0;
            *(float2*)(C + (size_t)(r0 + 8) * N + col) = v1;
        }
    }
}

// ---------------------------------------------------------------------------
// RoPE + split qkv into per-head fp16 Q(hi/lo), K, V buffers [head][T][80].
// ---------------------------------------------------------------------------
__global__ void rope_split_kernel(const float* __restrict__ rope)
{
    int idx = blockIdx.x * blockDim.x + threadIdx.x;
    if (idx >= T * NH * HD) return;
    int d = idx % HD;
    int n = (idx / HD) % NH;
    int t = idx / (HD * NH);

    int dr = (d < 40) ? d : d - 40;
    float ang = rope[t * 40 + dr];
    float c = cosf(ang), s = sinf(ang);

    const float* qrow = g_qkv + (size_t)t * THID + n * HD;
    float qv, kv;
    if (d < 40) {
        qv = qrow[d] * c        - qrow[d + 40] * s;
        kv = qrow[HID + d] * c  - qrow[HID + d + 40] * s;
    } else {
        qv = qrow[d - 40] * s       + qrow[d] * c;
        kv = qrow[HID + d - 40] * s + qrow[HID + d] * c;
    }
    float vv = qrow[2 * HID + d];
    int o = (n * T + t) * HD + d;
    __half qh = __float2half_rn(qv);
    g_q16h[o] = qh;
    g_q16l[o] = __float2half_rn(qv - __half2float(qh));
    g_k16[o] = __float2half_rn(kv);
    g_v16[o] = __float2half_rn(vv);
}

// ---------------------------------------------------------------------------
// Tensor-core flash attention, block-diagonal masking. Round 13:
// fp16 asymmetric — QK^T = (Qh+Ql)·K (2 MMAs), PV = P·V (1 MMA).
// Per-tile MMAs halved vs bf16 3-term (120 -> 60). smem stage 11264 B
// (K 5632 + V 5632). Q hi/lo transiently occupies both stage regions.
// ---------------------------------------------------------------------------
#define KVSB 176            // 88 fp16 row stride (bytes), conflict-free ldmatrix
#define STG  11264          // K tile + V tile per stage

__device__ __forceinline__ void attn_prefetch(char* sm_, int sbuf, int n, int kb,
                                              const int* __restrict__ seg,
                                              int tid, int* segk)
{
    char* dst = sm_ + sbuf * STG;
    #pragma unroll
    for (int i = 0; i < 5; i++) {
        int c = tid + i * 128;             // 0..639
        int arr = c / 320, w = c % 320;    // 0=K, 1=V
        int key = w / 10, cb = (w % 10) * 16;
        int kg = kb + key;
        uint4 v = make_uint4(0u, 0u, 0u, 0u);
        const __half* base = (arr == 0) ? g_k16 : g_v16;
        if (kg < T)
            v = *(const uint4*)((const char*)(base + (size_t)(n * T + kg) * HD) + cb);
        *(uint4*)(dst + arr * 5632 + key * KVSB + cb) = v;
    }
    if (tid < 32) segk[sbuf * 32 + tid] = (kb + tid < T) ? seg[kb + tid] : -1;
}

__global__ __launch_bounds__(128)
void attn_mma_kernel(const int* __restrict__ seg)
{
    __shared__ __align__(16) char sm_[2 * STG + 256];
    int* segk = (int*)(sm_ + 2 * STG);
    const uint32_t sb0 = smem_to_u32(sm_);

    const int n = blockIdx.y;
    const int q0 = blockIdx.x * 64;
    const int tid = threadIdx.x;
    const int lane = tid & 31;
    const int wid = tid >> 5;
    const int wr = wid * 16;

    const int seg_lo = seg[q0], seg_hi = seg[q0 + 63];
    int lo = 0, hi = T;
    while (lo < hi) { int mid = (lo + hi) >> 1; if (seg[mid] < seg_lo) lo = mid + 1; else hi = mid; }
    const int kstart = lo;
    hi = T;
    while (lo < hi) { int mid = (lo + hi) >> 1; if (seg[mid] <= seg_hi) lo = mid + 1; else hi = mid; }
    const int kend = lo;
    const int kb0 = kstart & ~31;
    const int n_tiles = (kend - kb0 + 31) >> 5;

    const int myseg0 = seg[q0 + wr + (lane >> 2)];
    const int myseg1 = seg[q0 + wr + (lane >> 2) + 8];

    // ---- prologue: Q hi -> stage0 region, Q lo -> stage1 region (transient)
    {
        const char* gq_h = (const char*)(g_q16h + (size_t)(n * T + q0) * HD);
        const char* gq_l = (const char*)(g_q16l + (size_t)(n * T + q0) * HD);
        #pragma unroll
        for (int i = 0; i < 5; i++) {
            int c = tid + i * 128;            // 0..639 (64 rows x 10 chunks)
            int row = c / 10, cb = (c % 10) * 16;
            *(uint4*)(sm_ + row * KVSB + cb)       = *(const uint4*)(gq_h + row * 160 + cb);
            *(uint4*)(sm_ + STG + row * KVSB + cb) = *(const uint4*)(gq_l + row * 160 + cb);
        }
    }
    __syncthreads();

    uint32_t qfh[5][4], qfl[5][4];
    {
        uint32_t base_h = sb0 + (uint32_t)(wr + (lane & 15)) * KVSB + ((lane >> 4) * 8) * 2;
        uint32_t base_l = base_h + STG;
        #pragma unroll
        for (int ks = 0; ks < 5; ks++) {
            ldsm_x4(qfh[ks], base_h + ks * 32);
            ldsm_x4(qfl[ks], base_l + ks * 32);
        }
    }
    __syncthreads();   // Q regions free for KV stages

    attn_prefetch(sm_, 0, n, kb0, seg, tid, segk);
    __syncthreads();

    float OC[10][4];
    #pragma unroll
    for (int i = 0; i < 10; i++) { OC[i][0] = OC[i][1] = OC[i][2] = OC[i][3] = 0.f; }
    float m0 = -1e30f, m1 = -1e30f, l0 = 0.f, l1 = 0.f;
    const float scale = 0.11180339887498949f;   // 1/sqrt(80)

    for (int t = 0; t < n_tiles; t++) {
        if (t + 1 < n_tiles) attn_prefetch(sm_, (t + 1) & 1, n, kb0 + (t + 1) * 32, seg, tid, segk);
        const uint32_t sb = sb0 + (t & 1) * STG;
        const int* sgk = segk + (t & 1) * 32;

        // ---- S = (Qh+Ql) K^T, 4 n8-groups of keys
        float SC[4][4];
        #pragma unroll
        for (int g = 0; g < 4; g++) SC[g][0] = SC[g][1] = SC[g][2] = SC[g][3] = 0.f;

        const int krow = ((lane & 16) >> 1) + (lane & 7);
        #pragma unroll
        for (int ks = 0; ks < 5; ks++) {
            const int dimb = (ks * 16 + ((lane >> 3) & 1) * 8) * 2;
            #pragma unroll
            for (int gp = 0; gp < 2; gp++) {
                uint32_t kh[4];
                uint32_t a = sb + (uint32_t)(16 * gp + krow) * KVSB + dimb;
                ldsm_x4(kh, a);
                #pragma unroll
                for (int h = 0; h < 2; h++) {
                    int g = 2 * gp + h;
                    mma_f16(SC[g], qfh[ks], kh + 2 * h);
                    mma_f16(SC[g], qfl[ks], kh + 2 * h);
                }
            }
        }

        // ---- mask + online softmax
        float sM[4][4];
        #pragma unroll
        for (int g = 0; g < 4; g++) {
            int k0i = 8 * g + 2 * (lane & 3);
            int sA = sgk[k0i], sB = sgk[k0i + 1];
            sM[g][0] = (sA == myseg0) ? SC[g][0] * scale : -1e30f;
            sM[g][1] = (sB == myseg0) ? SC[g][1] * scale : -1e30f;
            sM[g][2] = (sA == myseg1) ? SC[g][2] * scale : -1e30f;
            sM[g][3] = (sB == myseg1) ? SC[g][3] * scale : -1e30f;
        }
        float cm0 = -1e30f, cm1 = -1e30f;
        #pragma unroll
        for (int g = 0; g < 4; g++) {
            cm0 = fmaxf(cm0, fmaxf(sM[g][0], sM[g][1]));
            cm1 = fmaxf(cm1, fmaxf(sM[g][2], sM[g][3]));
        }
        cm0 = fmaxf(cm0, __shfl_xor_sync(0xffffffffu, cm0, 1));
        cm0 = fmaxf(cm0, __shfl_xor_sync(0xffffffffu, cm0, 2));
        cm1 = fmaxf(cm1, __shfl_xor_sync(0xffffffffu, cm1, 1));
        cm1 = fmaxf(cm1, __shfl_xor_sync(0xffffffffu, cm1, 2));
        float nm0 = fmaxf(m0, cm0), nm1 = fmaxf(m1, cm1);
        float f0 = __expf(m0 - nm0), f1 = __expf(m1 - nm1);
        m0 = nm0; m1 = nm1;
        l0 *= f0; l1 *= f1;
        #pragma unroll
        for (int i = 0; i < 10; i++) {
            OC[i][0] *= f0; OC[i][1] *= f0; OC[i][2] *= f1; OC[i][3] *= f1;
        }

        float p[4][4];
        #pragma unroll
        for (int g = 0; g < 4; g++) {
            p[g][0] = __expf(sM[g][0] - m0); p[g][1] = __expf(sM[g][1] - m0);
            p[g][2] = __expf(sM[g][2] - m1); p[g][3] = __expf(sM[g][3] - m1);
            l0 += p[g][0] + p[g][1];
            l1 += p[g][2] + p[g][3];
        }

        // ---- pack P -> single fp16 A-fragments (2 k16 steps over 32 keys)
        uint32_t pa[2][4];
        #pragma unroll
        for (int ks2 = 0; ks2 < 2; ks2++) {
            #pragma unroll
            for (int pos = 0; pos < 4; pos++) {
                int g = 2 * ks2 + (pos >> 1);
                int e = (pos & 1) * 2;
                pa[ks2][pos] = packh(p[g][e], p[g][e + 1]);
            }
        }

        // ---- O += P V (single term), 10 n8-groups of dims
        #pragma unroll
        for (int ks2 = 0; ks2 < 2; ks2++) {
            const int vkey = 16 * ks2 + (lane & 15);
            const int vhalf = ((lane >> 4) & 1) * 16;
            #pragma unroll
            for (int dp = 0; dp < 5; dp++) {
                uint32_t vh[4];
                uint32_t a = sb + 5632 + (uint32_t)vkey * KVSB + dp * 32 + vhalf;
                ldsm_x4_t(vh, a);
                mma_f16(OC[2*dp],     pa[ks2], vh + 0);
                mma_f16(OC[2*dp + 1], pa[ks2], vh + 2);
            }
        }
        __syncthreads();
    }

    // ---- epilogue: normalize, fp16 hi/lo att output (proj A operand)
    l0 += __shfl_xor_sync(0xffffffffu, l0, 1);
    l0 += __shfl_xor_sync(0xffffffffu, l0, 2);
    l1 += __shfl_xor_sync(0xffffffffu, l1, 1);
    l1 += __shfl_xor_sync(0xffffffffu, l1, 2);
    float inv0 = 1.f / l0, inv1 = 1.f / l1;
    const int row0 = q0 + wr + (lane >> 2);
    const int colb = n * HD + 2 * (lane & 3);
    #pragma unroll
    for (int ng = 0; ng < 10; ng++) {
        int col = colb + 8 * ng;
        float v0 = OC[ng][0] * inv0, v1 = OC[ng][1] * inv0;
        float v2 = OC[ng][2] * inv1, v3 = OC[ng][3] * inv1;
        __half h0 = __float2half_rn(v0), h1 = __float2half_rn(v1);
        __half h2 = __float2half_rn(v2), h3 = __float2half_rn(v3);
        *(__half2*)(g_ah + (size_t)row0 * HID + col) = __halves2half2(h0, h1);
        *(__half2*)(g_al + (size_t)row0 * HID + col) =
            __halves2half2(__float2half_rn(v0 - __half2float(h0)),
                           __float2half_rn(v1 - __half2float(h1)));
        *(__half2*)(g_ah + (size_t)(row0 + 8) * HID + col) = __halves2half2(h2, h3);
        *(__half2*)(g_al + (size_t)(row0 + 8) * HID + col) =
            __halves2half2(__float2half_rn(v2 - __half2float(h2)),
                           __float2half_rn(v3 - __half2float(h3)));
    }
}

// ---------------------------------------------------------------------------
extern "C" void kernel_launch(void* const* d_in, const int* in_sizes, int n_in,
                              void* d_out, int out_size)
{
    const float* x     = (const float*)d_in[0];
    const float* rope  = (const float*)d_in[1];
    const int*   seg   = (const int*)  d_in[2];
    const float* qkvW  = (const float*)d_in[3];
    const float* qkvB  = (const float*)d_in[4];
    const float* projW = (const float*)d_in[5];
    const float* projB = (const float*)d_in[6];
    float* out = (float*)d_out;

    float* p_qkv;
    cudaGetSymbolAddress((void**)&p_qkv, g_qkv);
    __half *p_xh, *p_xl, *p_wq, *p_wp, *p_ah, *p_al;
    cudaGetSymbolAddress((void**)&p_xh, g_xh); cudaGetSymbolAddress((void**)&p_xl, g_xl);
    cudaGetSymbolAddress((void**)&p_wq, g_wq); cudaGetSymbolAddress((void**)&p_wp, g_wp);
    cudaGetSymbolAddress((void**)&p_ah, g_ah); cudaGetSymbolAddress((void**)&p_al, g_al);

    cudaFuncSetAttribute(gemm_f16split_kernel,
                         cudaFuncAttributeMaxDynamicSharedMemorySize, GEMM_SMEM);

    // 0. convert inputs (A: fp16 hi/lo split; B: transposed single fp16)
    convert_splitA_kernel<<<(T*HID + 255)/256, 256>>>(x, p_xh, p_xl, T*HID);
    convertT_kernel<<<dim3(THID/32, HID/32), dim3(32, 8)>>>(qkvW, p_wq, HID, THID);
    convertT_kernel<<<dim3(HID/32, HID/32), dim3(32, 8)>>>(projW, p_wp, HID, HID);

    // 1. qkv = x @ Wqkv + b   (fp16 asymmetric 2-term)
    gemm_f16split_kernel<<<dim3(THID/BN, T/BM), 256, GEMM_SMEM>>>(
        p_xh, p_xl, p_wq, qkvB, p_qkv, T, THID, HID);

    // 2. RoPE + split into per-head fp16 Q(hi/lo), K, V
    rope_split_kernel<<<(T*NH*HD + 255)/256, 256>>>(rope);

    // 3. Tensor-core block-diagonal flash attention (fp16 asymmetric)
    attn_mma_kernel<<<dim3(T/64, NH), 128>>>(seg);

    // 4. out = att @ Wproj + b   (fp16 asymmetric 2-term)
    gemm_f16split_kernel<<<dim3(HID/BN, T/BM), 256, GEMM_SMEM>>>(
        p_ah, p_al, p_wp, projB, out, T, HID, HID);
}

// round 14
// speedup vs baseline: 1.5340x; 1.0033x over previous
#include <cuda_runtime.h>
#include <cuda_bf16.h>
#include <cuda_fp16.h>
#include <cstdint>
#include <math.h>

#define T 2048
#define HID 1280
#define NH 16
#define HD 80
#define THID (3*HID)

// ---------------- scratch (static device allocations only) ----------------
__device__ float g_qkv[T*THID];

__device__ __half g_xh[T*HID],  g_xl[T*HID];
__device__ __half g_wq[THID*HID];          // Wqkv^T [3840][1280] fp16
__device__ __half g_wp[HID*HID];           // Wproj^T [1280][1280] fp16
__device__ __half g_ah[T*HID],  g_al[T*HID];

// fp16 roped Q, K, V (all single fp16), per head: [head][T][80]
__device__ __half g_q16[NH*T*HD];
__device__ __half g_k16[NH*T*HD];
__device__ __half g_v16[NH*T*HD];

// ---------------- helpers ----------------
__device__ __forceinline__ uint32_t smem_to_u32(const void* p) {
    uint32_t a;
    asm("{ .reg .u64 tmp; cvta.to.shared.u64 tmp, %1; cvt.u32.u64 %0, tmp; }"
        : "=r"(a) : "l"(p));
    return a;
}
__device__ __forceinline__ void mma_f16(float* c, const uint32_t* a, const uint32_t* b) {
    asm volatile("mma.sync.aligned.m16n8k16.row.col.f32.f16.f16.f32 "
        "{%0,%1,%2,%3}, {%4,%5,%6,%7}, {%8,%9}, {%0,%1,%2,%3};"
        : "+f"(c[0]), "+f"(c[1]), "+f"(c[2]), "+f"(c[3])
        : "r"(a[0]), "r"(a[1]), "r"(a[2]), "r"(a[3]), "r"(b[0]), "r"(b[1]));
}
__device__ __forceinline__ void ldsm_x4(uint32_t* r, uint32_t addr) {
    asm volatile("ldmatrix.sync.aligned.m8n8.x4.shared.b16 {%0,%1,%2,%3}, [%4];"
        : "=r"(r[0]), "=r"(r[1]), "=r"(r[2]), "=r"(r[3]) : "r"(addr));
}
__device__ __forceinline__ void ldsm_x4_t(uint32_t* r, uint32_t addr) {
    asm volatile("ldmatrix.sync.aligned.m8n8.x4.trans.shared.b16 {%0,%1,%2,%3}, [%4];"
        : "=r"(r[0]), "=r"(r[1]), "=r"(r[2]), "=r"(r[3]) : "r"(addr));
}
__device__ __forceinline__ void cp_async16(uint32_t dst, const void* src) {
    asm volatile("cp.async.cg.shared.global [%0], [%1], 16;" :: "r"(dst), "l"(src));
}
#define CP_COMMIT() asm volatile("cp.async.commit_group;" ::: "memory")
#define CP_WAIT1()  asm volatile("cp.async.wait_group 1;" ::: "memory")
__device__ __forceinline__ uint32_t packh(float lo_, float hi_) {
    uint32_t r;
    asm("cvt.rn.f16x2.f32 %0, %1, %2;" : "=r"(r) : "f"(hi_), "f"(lo_));
    return r;
}

// ---------------------------------------------------------------------------
// fp32 -> fp16 hi + fp16 lo split (GEMM A operands)
// ---------------------------------------------------------------------------
__global__ void convert_splitA_kernel(const float* __restrict__ src,
                                      __half* __restrict__ h,
                                      __half* __restrict__ l, int n)
{
    int i = blockIdx.x * blockDim.x + threadIdx.x;
    if (i >= n) return;
    float v = src[i];
    __half hh = __float2half_rn(v);
    h[i] = hh;
    l[i] = __float2half_rn(v - __half2float(hh));
}

// Transpose [K][N] -> [N][K], single fp16 (GEMM B operand)
__global__ void convertT_kernel(const float* __restrict__ src,
                                __half* __restrict__ h,
                                int K, int N)
{
    __shared__ float t[32][33];
    int nb = blockIdx.x * 32, kb = blockIdx.y * 32;
    int tx = threadIdx.x, ty = threadIdx.y;   // (32, 8)
    #pragma unroll
    for (int j = 0; j < 4; j++)
        t[ty + j * 8][tx] = src[(size_t)(kb + ty + j * 8) * N + nb + tx];
    __syncthreads();
    #pragma unroll
    for (int j = 0; j < 4; j++)
        h[(size_t)(nb + ty + j * 8) * K + kb + tx] = __float2half_rn(t[tx][ty + j * 8]);
}

// ---------------------------------------------------------------------------
// fp16 tensor-core GEMM, TERMS = 1 or 2:
//   C = (Ah [+ Al]) @ Bh^T + bias     (B/bias/C pointers pre-offset by caller)
// Round-9 pipeline config (BM=64, 2-stage, 3 CTA/SM).
// ---------------------------------------------------------------------------
#define BM 64
#define BN 128
#define BK 32
#define ASTRIDE 40
#define A_TILE (64*80)
#define B_TILE (128*80)
#define STAGE_B (2*A_TILE + B_TILE)      // 20480 B
#define GEMM_SMEM (2*STAGE_B)            // 40960 B

template<int TERMS>
__global__ __launch_bounds__(256, 3)
void gemm_f16_kernel(const __half* __restrict__ Ah,
                     const __half* __restrict__ Al,
                     const __half* __restrict__ Bh,
                     const float* __restrict__ bias,
                     float* __restrict__ C,
                     int ldC, int K)
{
    extern __shared__ char sm[];
    const uint32_t sbase = smem_to_u32(sm);

    const int tid  = threadIdx.x;
    const int wid  = tid >> 5;
    const int lane = tid & 31;
    const int m0 = blockIdx.y * BM, n0 = blockIdx.x * BN;
    const int wm = (wid >> 1) * 16;
    const int wn = (wid & 1) * 64;

    float acc[8][4];
    #pragma unroll
    for (int b = 0; b < 8; b++)
        #pragma unroll
        for (int c = 0; c < 4; c++) acc[b][c] = 0.f;

    const int c_row = tid >> 2;
    const int c_col = (tid & 3) * 8;
    const uint32_t s_off  = (uint32_t)(c_row * ASTRIDE + c_col) * 2;
    const uint32_t s_off2 = s_off + (uint32_t)64 * ASTRIDE * 2;

    const __half* gAh = Ah + (size_t)(m0 + c_row) * K + c_col;
    const __half* gAl = (TERMS == 2) ? (Al + (size_t)(m0 + c_row) * K + c_col) : gAh;
    const __half* gBh = Bh + (size_t)(n0 + c_row) * K + c_col;
    const size_t g2 = (size_t)64 * K;

    const int niter = K / BK;

    {
        uint32_t sb = sbase;
        cp_async16(sb + s_off,              gAh);
        if (TERMS == 2) cp_async16(sb + A_TILE + s_off, gAl);
        cp_async16(sb + 2*A_TILE + s_off,   gBh);
        cp_async16(sb + 2*A_TILE + s_off2,  gBh + g2);
    }
    CP_COMMIT();

    const int a_row  = (lane & 15);
    const int a_colb = (lane >> 4) * 16;
    const int b_row  = (lane & 7) + ((lane >> 4) << 3);
    const int b_colb = (((lane >> 3) & 1)) * 16;

    for (int it = 0; it < niter; it++) {
        int nk = it + 1;
        if (nk < niter) {
            uint32_t sb = sbase + (nk & 1) * STAGE_B;
            int k0 = nk * BK;
            cp_async16(sb + s_off,              gAh + k0);
            if (TERMS == 2) cp_async16(sb + A_TILE + s_off, gAl + k0);
            cp_async16(sb + 2*A_TILE + s_off,   gBh + k0);
            cp_async16(sb + 2*A_TILE + s_off2,  gBh + g2 + k0);
        }
        CP_COMMIT();
        CP_WAIT1();
        __syncthreads();

        const uint32_t sb  = sbase + (it & 1) * STAGE_B;
        const uint32_t sAh = sb;
        const uint32_t sAl = sb + A_TILE;
        const uint32_t sBh = sb + 2*A_TILE;

        #pragma unroll
        for (int k16 = 0; k16 < 2; k16++) {
            const int kcb = k16 * 32;
            uint32_t ah[4], al[4];
            {
                uint32_t ro = (uint32_t)(wm + a_row) * 80 + kcb + a_colb;
                ldsm_x4(ah, sAh + ro);
                if (TERMS == 2) ldsm_x4(al, sAl + ro);
            }
            #pragma unroll
            for (int g = 0; g < 4; g++) {
                uint32_t ro = (uint32_t)(wn + g*16 + b_row) * 80 + kcb + b_colb;
                uint32_t bh[4];
                ldsm_x4(bh, sBh + ro);
                mma_f16(acc[g*2+0], ah, bh + 0);
                mma_f16(acc[g*2+1], ah, bh + 2);
                if (TERMS == 2) {
                    mma_f16(acc[g*2+0], al, bh + 0);
                    mma_f16(acc[g*2+1], al, bh + 2);
                }
            }
        }
        __syncthreads();
    }

    {
        int r0 = m0 + wm + (lane >> 2);
        #pragma unroll
        for (int t = 0; t < 8; t++) {
            int col = n0 + wn + t*8 + (lane & 3)*2;
            float b0 = bias[col], b1 = bias[col + 1];
            float2 v0 = { acc[t][0] + b0, acc[t][1] + b1 };
            float2 v1 = { acc[t][2] + b0, acc[t][3] + b1 };
            *(float2*)(C + (size_t)r0 * ldC + col)       = v0;
            *(float2*)(C + (size_t)(r0 + 8) * ldC + col) = v1;
        }
    }
}

// ---------------------------------------------------------------------------
// RoPE + split qkv into per-head fp16 Q, K, V buffers [head][T][80].
// ---------------------------------------------------------------------------
__global__ void rope_split_kernel(const float* __restrict__ rope)
{
    int idx = blockIdx.x * blockDim.x + threadIdx.x;
    if (idx >= T * NH * HD) return;
    int d = idx % HD;
    int n = (idx / HD) % NH;
    int t = idx / (HD * NH);

    int dr = (d < 40) ? d : d - 40;
    float ang = rope[t * 40 + dr];
    float c = cosf(ang), s = sinf(ang);

    const float* qrow = g_qkv + (size_t)t * THID + n * HD;
    float qv, kv;
    if (d < 40) {
        qv = qrow[d] * c        - qrow[d + 40] * s;
        kv = qrow[HID + d] * c  - qrow[HID + d + 40] * s;
    } else {
        qv = qrow[d - 40] * s       + qrow[d] * c;
        kv = qrow[HID + d - 40] * s + qrow[HID + d] * c;
    }
    float vv = qrow[2 * HID + d];
    int o = (n * T + t) * HD + d;
    g_q16[o] = __float2half_rn(qv);
    g_k16[o] = __float2half_rn(kv);
    g_v16[o] = __float2half_rn(vv);
}

// ---------------------------------------------------------------------------
// Tensor-core flash attention, block-diagonal masking. Round 14:
// fully single fp16 — QK^T = Q·K (1 MMA), PV = P·V (1 MMA). 40 MMAs/tile.
// ---------------------------------------------------------------------------
#define KVSB 176            // 88 fp16 row stride (bytes)
#define STG  11264          // K tile + V tile per stage

__device__ __forceinline__ void attn_prefetch(char* sm_, int sbuf, int n, int kb,
                                              const int* __restrict__ seg,
                                              int tid, int* segk)
{
    char* dst = sm_ + sbuf * STG;
    #pragma unroll
    for (int i = 0; i < 5; i++) {
        int c = tid + i * 128;             // 0..639
        int arr = c / 320, w = c % 320;    // 0=K, 1=V
        int key = w / 10, cb = (w % 10) * 16;
        int kg = kb + key;
        uint4 v = make_uint4(0u, 0u, 0u, 0u);
        const __half* base = (arr == 0) ? g_k16 : g_v16;
        if (kg < T)
            v = *(const uint4*)((const char*)(base + (size_t)(n * T + kg) * HD) + cb);
        *(uint4*)(dst + arr * 5632 + key * KVSB + cb) = v;
    }
    if (tid < 32) segk[sbuf * 32 + tid] = (kb + tid < T) ? seg[kb + tid] : -1;
}

__global__ __launch_bounds__(128)
void attn_mma_kernel(const int* __restrict__ seg)
{
    __shared__ __align__(16) char sm_[2 * STG + 256];
    int* segk = (int*)(sm_ + 2 * STG);
    const uint32_t sb0 = smem_to_u32(sm_);

    const int n = blockIdx.y;
    const int q0 = blockIdx.x * 64;
    const int tid = threadIdx.x;
    const int lane = tid & 31;
    const int wid = tid >> 5;
    const int wr = wid * 16;

    const int seg_lo = seg[q0], seg_hi = seg[q0 + 63];
    int lo = 0, hi = T;
    while (lo < hi) { int mid = (lo + hi) >> 1; if (seg[mid] < seg_lo) lo = mid + 1; else hi = mid; }
    const int kstart = lo;
    hi = T;
    while (lo < hi) { int mid = (lo + hi) >> 1; if (seg[mid] <= seg_hi) lo = mid + 1; else hi = mid; }
    const int kend = lo;
    const int kb0 = kstart & ~31;
    const int n_tiles = (kend - kb0 + 31) >> 5;

    const int myseg0 = seg[q0 + wr + (lane >> 2)];
    const int myseg1 = seg[q0 + wr + (lane >> 2) + 8];

    // ---- prologue: Q -> stage1 region (transient), tile 0 -> stage0
    {
        const char* gq = (const char*)(g_q16 + (size_t)(n * T + q0) * HD);
        #pragma unroll
        for (int i = 0; i < 5; i++) {
            int c = tid + i * 128;            // 0..639 (64 rows x 10 chunks)
            int row = c / 10, cb = (c % 10) * 16;
            *(uint4*)(sm_ + STG + row * KVSB + cb) = *(const uint4*)(gq + row * 160 + cb);
        }
    }
    attn_prefetch(sm_, 0, n, kb0, seg, tid, segk);
    __syncthreads();

    uint32_t qf[5][4];
    {
        uint32_t base_q = sb0 + STG + (uint32_t)(wr + (lane & 15)) * KVSB + ((lane >> 4) * 8) * 2;
        #pragma unroll
        for (int ks = 0; ks < 5; ks++)
            ldsm_x4(qf[ks], base_q + ks * 32);
    }
    __syncthreads();   // stage1 region free for prefetch

    float OC[10][4];
    #pragma unroll
    for (int i = 0; i < 10; i++) { OC[i][0] = OC[i][1] = OC[i][2] = OC[i][3] = 0.f; }
    float m0 = -1e30f, m1 = -1e30f, l0 = 0.f, l1 = 0.f;
    const float scale = 0.11180339887498949f;   // 1/sqrt(80)

    for (int t = 0; t < n_tiles; t++) {
        if (t + 1 < n_tiles) attn_prefetch(sm_, (t + 1) & 1, n, kb0 + (t + 1) * 32, seg, tid, segk);
        const uint32_t sb = sb0 + (t & 1) * STG;
        const int* sgk = segk + (t & 1) * 32;

        // ---- S = Q K^T (single term)
        float SC[4][4];
        #pragma unroll
        for (int g = 0; g < 4; g++) SC[g][0] = SC[g][1] = SC[g][2] = SC[g][3] = 0.f;

        const int krow = ((lane & 16) >> 1) + (lane & 7);
        #pragma unroll
        for (int ks = 0; ks < 5; ks++) {
            const int dimb = (ks * 16 + ((lane >> 3) & 1) * 8) * 2;
            #pragma unroll
            for (int gp = 0; gp < 2; gp++) {
                uint32_t kh[4];
                uint32_t a = sb + (uint32_t)(16 * gp + krow) * KVSB + dimb;
                ldsm_x4(kh, a);
                mma_f16(SC[2*gp+0], qf[ks], kh + 0);
                mma_f16(SC[2*gp+1], qf[ks], kh + 2);
            }
        }

        // ---- mask + online softmax
        float sM[4][4];
        #pragma unroll
        for (int g = 0; g < 4; g++) {
            int k0i = 8 * g + 2 * (lane & 3);
            int sA = sgk[k0i], sB = sgk[k0i + 1];
            sM[g][0] = (sA == myseg0) ? SC[g][0] * scale : -1e30f;
            sM[g][1] = (sB == myseg0) ? SC[g][1] * scale : -1e30f;
            sM[g][2] = (sA == myseg1) ? SC[g][2] * scale : -1e30f;
            sM[g][3] = (sB == myseg1) ? SC[g][3] * scale : -1e30f;
        }
        float cm0 = -1e30f, cm1 = -1e30f;
        #pragma unroll
        for (int g = 0; g < 4; g++) {
            cm0 = fmaxf(cm0, fmaxf(sM[g][0], sM[g][1]));
            cm1 = fmaxf(cm1, fmaxf(sM[g][2], sM[g][3]));
        }
        cm0 = fmaxf(cm0, __shfl_xor_sync(0xffffffffu, cm0, 1));
        cm0 = fmaxf(cm0, __shfl_xor_sync(0xffffffffu, cm0, 2));
        cm1 = fmaxf(cm1, __shfl_xor_sync(0xffffffffu, cm1, 1));
        cm1 = fmaxf(cm1, __shfl_xor_sync(0xffffffffu, cm1, 2));
        float nm0 = fmaxf(m0, cm0), nm1 = fmaxf(m1, cm1);
        float f0 = __expf(m0 - nm0), f1 = __expf(m1 - nm1);
        m0 = nm0; m1 = nm1;
        l0 *= f0; l1 *= f1;
        #pragma unroll
        for (int i = 0; i < 10; i++) {
            OC[i][0] *= f0; OC[i][1] *= f0; OC[i][2] *= f1; OC[i][3] *= f1;
        }

        float p[4][4];
        #pragma unroll
        for (int g = 0; g < 4; g++) {
            p[g][0] = __expf(sM[g][0] - m0); p[g][1] = __expf(sM[g][1] - m0);
            p[g][2] = __expf(sM[g][2] - m1); p[g][3] = __expf(sM[g][3] - m1);
            l0 += p[g][0] + p[g][1];
            l1 += p[g][2] + p[g][3];
        }

        // ---- pack P -> single fp16 A-fragments
        uint32_t pa[2][4];
        #pragma unroll
        for (int ks2 = 0; ks2 < 2; ks2++) {
            #pragma unroll
            for (int pos = 0; pos < 4; pos++) {
                int g = 2 * ks2 + (pos >> 1);
                int e = (pos & 1) * 2;
                pa[ks2][pos] = packh(p[g][e], p[g][e + 1]);
            }
        }

        // ---- O += P V (single term)
        #pragma unroll
        for (int ks2 = 0; ks2 < 2; ks2++) {
            const int vkey = 16 * ks2 + (lane & 15);
            const int vhalf = ((lane >> 4) & 1) * 16;
            #pragma unroll
            for (int dp = 0; dp < 5; dp++) {
                uint32_t vh[4];
                uint32_t a = sb + 5632 + (uint32_t)vkey * KVSB + dp * 32 + vhalf;
                ldsm_x4_t(vh, a);
                mma_f16(OC[2*dp],     pa[ks2], vh + 0);
                mma_f16(OC[2*dp + 1], pa[ks2], vh + 2);
            }
        }
        __syncthreads();
    }

    // ---- epilogue: normalize, fp16 hi/lo att output (proj A operand)
    l0 += __shfl_xor_sync(0xffffffffu, l0, 1);
    l0 += __shfl_xor_sync(0xffffffffu, l0, 2);
    l1 += __shfl_xor_sync(0xffffffffu, l1, 1);
    l1 += __shfl_xor_sync(0xffffffffu, l1, 2);
    float inv0 = 1.f / l0, inv1 = 1.f / l1;
    const int row0 = q0 + wr + (lane >> 2);
    const int colb = n * HD + 2 * (lane & 3);
    #pragma unroll
    for (int ng = 0; ng < 10; ng++) {
        int col = colb + 8 * ng;
        float v0 = OC[ng][0] * inv0, v1 = OC[ng][1] * inv0;
        float v2 = OC[ng][2] * inv1, v3 = OC[ng][3] * inv1;
        __half h0 = __float2half_rn(v0), h1 = __float2half_rn(v1);
        __half h2 = __float2half_rn(v2), h3 = __float2half_rn(v3);
        *(__half2*)(g_ah + (size_t)row0 * HID + col) = __halves2half2(h0, h1);
        *(__half2*)(g_al + (size_t)row0 * HID + col) =
            __halves2half2(__float2half_rn(v0 - __half2float(h0)),
                           __float2half_rn(v1 - __half2float(h1)));
        *(__half2*)(g_ah + (size_t)(row0 + 8) * HID + col) = __halves2half2(h2, h3);
        *(__half2*)(g_al + (size_t)(row0 + 8) * HID + col) =
            __halves2half2(__float2half_rn(v2 - __half2float(h2)),
                           __float2half_rn(v3 - __half2float(h3)));
    }
}

// ---------------------------------------------------------------------------
extern "C" void kernel_launch(void* const* d_in, const int* in_sizes, int n_in,
                              void* d_out, int out_size)
{
    const float* x     = (const float*)d_in[0];
    const float* rope  = (const float*)d_in[1];
    const int*   seg   = (const int*)  d_in[2];
    const float* qkvW  = (const float*)d_in[3];
    const float* qkvB  = (const float*)d_in[4];
    const float* projW = (const float*)d_in[5];
    const float* projB = (const float*)d_in[6];
    float* out = (float*)d_out;

    float* p_qkv;
    cudaGetSymbolAddress((void**)&p_qkv, g_qkv);
    __half *p_xh, *p_xl, *p_wq, *p_wp, *p_ah, *p_al;
    cudaGetSymbolAddress((void**)&p_xh, g_xh); cudaGetSymbolAddress((void**)&p_xl, g_xl);
    cudaGetSymbolAddress((void**)&p_wq, g_wq); cudaGetSymbolAddress((void**)&p_wp, g_wp);
    cudaGetSymbolAddress((void**)&p_ah, g_ah); cudaGetSymbolAddress((void**)&p_al, g_al);

    cudaFuncSetAttribute(gemm_f16_kernel<2>,
                         cudaFuncAttributeMaxDynamicSharedMemorySize, GEMM_SMEM);
    cudaFuncSetAttribute(gemm_f16_kernel<1>,
                         cudaFuncAttributeMaxDynamicSharedMemorySize, GEMM_SMEM);

    // 0. converts
    convert_splitA_kernel<<<(T*HID + 255)/256, 256>>>(x, p_xh, p_xl, T*HID);
    convertT_kernel<<<dim3(THID/32, HID/32), dim3(32, 8)>>>(qkvW, p_wq, HID, THID);
    convertT_kernel<<<dim3(HID/32, HID/32), dim3(32, 8)>>>(projW, p_wp, HID, HID);

    // 1a. Q,K columns of qkv (N=2560): 2-term
    gemm_f16_kernel<2><<<dim3(2*HID/BN, T/BM), 256, GEMM_SMEM>>>(
        p_xh, p_xl, p_wq, qkvB, p_qkv, THID, HID);
    // 1b. V columns of qkv (N=1280): 1-term (V is rounded to fp16 downstream anyway)
    gemm_f16_kernel<1><<<dim3(HID/BN, T/BM), 256, GEMM_SMEM>>>(
        p_xh, nullptr, p_wq + (size_t)(2*HID) * HID, qkvB + 2*HID, p_qkv + 2*HID, THID, HID);

    // 2. RoPE + split into per-head fp16 Q, K, V
    rope_split_kernel<<<(T*NH*HD + 255)/256, 256>>>(rope);

    // 3. Tensor-core block-diagonal flash attention (all single fp16)
    attn_mma_kernel<<<dim3(T/64, NH), 128>>>(seg);

    // 4. out = att @ Wproj + b   (fp16 2-term — output precision matters)
    gemm_f16_kernel<2><<<dim3(HID/BN, T/BM), 256, GEMM_SMEM>>>(
        p_ah, p_al, p_wp, projB, out, HID, HID);
}

// round 15
// speedup vs baseline: 1.6487x; 1.0748x over previous
#include <cuda_runtime.h>
#include <cuda_bf16.h>
#include <cuda_fp16.h>
#include <cstdint>
#include <math.h>

#define T 2048
#define HID 1280
#define NH 16
#define HD 80
#define THID (3*HID)

// ---------------- scratch (static device allocations only) ----------------
__device__ float g_qkv[T*THID];

__device__ __half g_xh[T*HID],  g_xl[T*HID];
__device__ __half g_wq[THID*HID];          // Wqkv^T [3840][1280] fp16
__device__ __half g_wp[HID*HID];           // Wproj^T [1280][1280] fp16
__device__ __half g_att16[T*HID];          // attention output, single fp16

// fp16 roped Q, K, V (all single fp16), per head: [head][T][80]
__device__ __half g_q16[NH*T*HD];
__device__ __half g_k16[NH*T*HD];
__device__ __half g_v16[NH*T*HD];

// ---------------- helpers ----------------
__device__ __forceinline__ uint32_t smem_to_u32(const void* p) {
    uint32_t a;
    asm("{ .reg .u64 tmp; cvta.to.shared.u64 tmp, %1; cvt.u32.u64 %0, tmp; }"
        : "=r"(a) : "l"(p));
    return a;
}
__device__ __forceinline__ void mma_f16(float* c, const uint32_t* a, const uint32_t* b) {
    asm volatile("mma.sync.aligned.m16n8k16.row.col.f32.f16.f16.f32 "
        "{%0,%1,%2,%3}, {%4,%5,%6,%7}, {%8,%9}, {%0,%1,%2,%3};"
        : "+f"(c[0]), "+f"(c[1]), "+f"(c[2]), "+f"(c[3])
        : "r"(a[0]), "r"(a[1]), "r"(a[2]), "r"(a[3]), "r"(b[0]), "r"(b[1]));
}
__device__ __forceinline__ void ldsm_x4(uint32_t* r, uint32_t addr) {
    asm volatile("ldmatrix.sync.aligned.m8n8.x4.shared.b16 {%0,%1,%2,%3}, [%4];"
        : "=r"(r[0]), "=r"(r[1]), "=r"(r[2]), "=r"(r[3]) : "r"(addr));
}
__device__ __forceinline__ void ldsm_x4_t(uint32_t* r, uint32_t addr) {
    asm volatile("ldmatrix.sync.aligned.m8n8.x4.trans.shared.b16 {%0,%1,%2,%3}, [%4];"
        : "=r"(r[0]), "=r"(r[1]), "=r"(r[2]), "=r"(r[3]) : "r"(addr));
}
__device__ __forceinline__ void cp_async16(uint32_t dst, const void* src) {
    asm volatile("cp.async.cg.shared.global [%0], [%1], 16;" :: "r"(dst), "l"(src));
}
#define CP_COMMIT() asm volatile("cp.async.commit_group;" ::: "memory")
#define CP_WAIT1()  asm volatile("cp.async.wait_group 1;" ::: "memory")
__device__ __forceinline__ uint32_t packh(float lo_, float hi_) {
    uint32_t r;
    asm("cvt.rn.f16x2.f32 %0, %1, %2;" : "=r"(r) : "f"(hi_), "f"(lo_));
    return r;
}

// ---------------------------------------------------------------------------
// fp32 -> fp16 hi + fp16 lo split (x, the 2-term A operand)
// ---------------------------------------------------------------------------
__global__ void convert_splitA_kernel(const float* __restrict__ src,
                                      __half* __restrict__ h,
                                      __half* __restrict__ l, int n)
{
    int i = blockIdx.x * blockDim.x + threadIdx.x;
    if (i >= n) return;
    float v = src[i];
    __half hh = __float2half_rn(v);
    h[i] = hh;
    l[i] = __float2half_rn(v - __half2float(hh));
}

// Transpose [K][N] -> [N][K], single fp16 (GEMM B operand)
__global__ void convertT_kernel(const float* __restrict__ src,
                                __half* __restrict__ h,
                                int K, int N)
{
    __shared__ float t[32][33];
    int nb = blockIdx.x * 32, kb = blockIdx.y * 32;
    int tx = threadIdx.x, ty = threadIdx.y;   // (32, 8)
    #pragma unroll
    for (int j = 0; j < 4; j++)
        t[ty + j * 8][tx] = src[(size_t)(kb + ty + j * 8) * N + nb + tx];
    __syncthreads();
    #pragma unroll
    for (int j = 0; j < 4; j++)
        h[(size_t)(nb + ty + j * 8) * K + kb + tx] = __float2half_rn(t[tx][ty + j * 8]);
}

// ---------------------------------------------------------------------------
// fp16 tensor-core GEMM with per-block term count:
//   blocks with n0 <  nsplit : C = (Ah+Al) @ Bh^T + bias   (2-term)
//   blocks with n0 >= nsplit : C =  Ah     @ Bh^T + bias   (1-term)
// One launch covers mixed-precision column ranges with a single wave structure.
// ---------------------------------------------------------------------------
#define BM 64
#define BN 128
#define BK 32
#define ASTRIDE 40
#define A_TILE (64*80)
#define B_TILE (128*80)
#define STAGE_B (2*A_TILE + B_TILE)      // 20480 B
#define GEMM_SMEM (2*STAGE_B)            // 40960 B

__global__ __launch_bounds__(256, 3)
void gemm_f16_kernel(const __half* __restrict__ Ah,
                     const __half* __restrict__ Al,
                     const __half* __restrict__ Bh,
                     const float* __restrict__ bias,
                     float* __restrict__ C,
                     int ldC, int K, int nsplit)
{
    extern __shared__ char sm[];
    const uint32_t sbase = smem_to_u32(sm);

    const int tid  = threadIdx.x;
    const int wid  = tid >> 5;
    const int lane = tid & 31;
    const int m0 = blockIdx.y * BM, n0 = blockIdx.x * BN;
    const int wm = (wid >> 1) * 16;
    const int wn = (wid & 1) * 64;
    const bool t2 = (n0 < nsplit);        // block-uniform

    float acc[8][4];
    #pragma unroll
    for (int b = 0; b < 8; b++)
        #pragma unroll
        for (int c = 0; c < 4; c++) acc[b][c] = 0.f;

    const int c_row = tid >> 2;
    const int c_col = (tid & 3) * 8;
    const uint32_t s_off  = (uint32_t)(c_row * ASTRIDE + c_col) * 2;
    const uint32_t s_off2 = s_off + (uint32_t)64 * ASTRIDE * 2;

    const __half* gAh = Ah + (size_t)(m0 + c_row) * K + c_col;
    const __half* gAl = Al + (size_t)(m0 + c_row) * K + c_col;
    const __half* gBh = Bh + (size_t)(n0 + c_row) * K + c_col;
    const size_t g2 = (size_t)64 * K;

    const int niter = K / BK;

    {
        uint32_t sb = sbase;
        cp_async16(sb + s_off,              gAh);
        if (t2) cp_async16(sb + A_TILE + s_off, gAl);
        cp_async16(sb + 2*A_TILE + s_off,   gBh);
        cp_async16(sb + 2*A_TILE + s_off2,  gBh + g2);
    }
    CP_COMMIT();

    const int a_row  = (lane & 15);
    const int a_colb = (lane >> 4) * 16;
    const int b_row  = (lane & 7) + ((lane >> 4) << 3);
    const int b_colb = (((lane >> 3) & 1)) * 16;

    for (int it = 0; it < niter; it++) {
        int nk = it + 1;
        if (nk < niter) {
            uint32_t sb = sbase + (nk & 1) * STAGE_B;
            int k0 = nk * BK;
            cp_async16(sb + s_off,              gAh + k0);
            if (t2) cp_async16(sb + A_TILE + s_off, gAl + k0);
            cp_async16(sb + 2*A_TILE + s_off,   gBh + k0);
            cp_async16(sb + 2*A_TILE + s_off2,  gBh + g2 + k0);
        }
        CP_COMMIT();
        CP_WAIT1();
        __syncthreads();

        const uint32_t sb  = sbase + (it & 1) * STAGE_B;
        const uint32_t sAh = sb;
        const uint32_t sAl = sb + A_TILE;
        const uint32_t sBh = sb + 2*A_TILE;

        #pragma unroll
        for (int k16 = 0; k16 < 2; k16++) {
            const int kcb = k16 * 32;
            uint32_t ah[4], al[4];
            {
                uint32_t ro = (uint32_t)(wm + a_row) * 80 + kcb + a_colb;
                ldsm_x4(ah, sAh + ro);
                if (t2) ldsm_x4(al, sAl + ro);
            }
            #pragma unroll
            for (int g = 0; g < 4; g++) {
                uint32_t ro = (uint32_t)(wn + g*16 + b_row) * 80 + kcb + b_colb;
                uint32_t bh[4];
                ldsm_x4(bh, sBh + ro);
                mma_f16(acc[g*2+0], ah, bh + 0);
                mma_f16(acc[g*2+1], ah, bh + 2);
                if (t2) {
                    mma_f16(acc[g*2+0], al, bh + 0);
                    mma_f16(acc[g*2+1], al, bh + 2);
                }
            }
        }
        __syncthreads();
    }

    {
        int r0 = m0 + wm + (lane >> 2);
        #pragma unroll
        for (int t = 0; t < 8; t++) {
            int col = n0 + wn + t*8 + (lane & 3)*2;
            float b0 = bias[col], b1 = bias[col + 1];
            float2 v0 = { acc[t][0] + b0, acc[t][1] + b1 };
            float2 v1 = { acc[t][2] + b0, acc[t][3] + b1 };
            *(float2*)(C + (size_t)r0 * ldC + col)       = v0;
            *(float2*)(C + (size_t)(r0 + 8) * ldC + col) = v1;
        }
    }
}

// ---------------------------------------------------------------------------
// RoPE + split qkv into per-head fp16 Q, K, V buffers [head][T][80].
// ---------------------------------------------------------------------------
__global__ void rope_split_kernel(const float* __restrict__ rope)
{
    int idx = blockIdx.x * blockDim.x + threadIdx.x;
    if (idx >= T * NH * HD) return;
    int d = idx % HD;
    int n = (idx / HD) % NH;
    int t = idx / (HD * NH);

    int dr = (d < 40) ? d : d - 40;
    float ang = rope[t * 40 + dr];
    float c = cosf(ang), s = sinf(ang);

    const float* qrow = g_qkv + (size_t)t * THID + n * HD;
    float qv, kv;
    if (d < 40) {
        qv = qrow[d] * c        - qrow[d + 40] * s;
        kv = qrow[HID + d] * c  - qrow[HID + d + 40] * s;
    } else {
        qv = qrow[d - 40] * s       + qrow[d] * c;
        kv = qrow[HID + d - 40] * s + qrow[HID + d] * c;
    }
    float vv = qrow[2 * HID + d];
    int o = (n * T + t) * HD + d;
    g_q16[o] = __float2half_rn(qv);
    g_k16[o] = __float2half_rn(kv);
    g_v16[o] = __float2half_rn(vv);
}

// ---------------------------------------------------------------------------
// Tensor-core flash attention (single fp16, 40 MMAs/tile) — proven round 14.
// Epilogue writes single fp16 att (proj is 1-term now).
// ---------------------------------------------------------------------------
#define KVSB 176
#define STG  11264

__device__ __forceinline__ void attn_prefetch(char* sm_, int sbuf, int n, int kb,
                                              const int* __restrict__ seg,
                                              int tid, int* segk)
{
    char* dst = sm_ + sbuf * STG;
    #pragma unroll
    for (int i = 0; i < 5; i++) {
        int c = tid + i * 128;
        int arr = c / 320, w = c % 320;    // 0=K, 1=V
        int key = w / 10, cb = (w % 10) * 16;
        int kg = kb + key;
        uint4 v = make_uint4(0u, 0u, 0u, 0u);
        const __half* base = (arr == 0) ? g_k16 : g_v16;
        if (kg < T)
            v = *(const uint4*)((const char*)(base + (size_t)(n * T + kg) * HD) + cb);
        *(uint4*)(dst + arr * 5632 + key * KVSB + cb) = v;
    }
    if (tid < 32) segk[sbuf * 32 + tid] = (kb + tid < T) ? seg[kb + tid] : -1;
}

__global__ __launch_bounds__(128)
void attn_mma_kernel(const int* __restrict__ seg)
{
    __shared__ __align__(16) char sm_[2 * STG + 256];
    int* segk = (int*)(sm_ + 2 * STG);
    const uint32_t sb0 = smem_to_u32(sm_);

    const int n = blockIdx.y;
    const int q0 = blockIdx.x * 64;
    const int tid = threadIdx.x;
    const int lane = tid & 31;
    const int wid = tid >> 5;
    const int wr = wid * 16;

    const int seg_lo = seg[q0], seg_hi = seg[q0 + 63];
    int lo = 0, hi = T;
    while (lo < hi) { int mid = (lo + hi) >> 1; if (seg[mid] < seg_lo) lo = mid + 1; else hi = mid; }
    const int kstart = lo;
    hi = T;
    while (lo < hi) { int mid = (lo + hi) >> 1; if (seg[mid] <= seg_hi) lo = mid + 1; else hi = mid; }
    const int kend = lo;
    const int kb0 = kstart & ~31;
    const int n_tiles = (kend - kb0 + 31) >> 5;

    const int myseg0 = seg[q0 + wr + (lane >> 2)];
    const int myseg1 = seg[q0 + wr + (lane >> 2) + 8];

    {
        const char* gq = (const char*)(g_q16 + (size_t)(n * T + q0) * HD);
        #pragma unroll
        for (int i = 0; i < 5; i++) {
            int c = tid + i * 128;
            int row = c / 10, cb = (c % 10) * 16;
            *(uint4*)(sm_ + STG + row * KVSB + cb) = *(const uint4*)(gq + row * 160 + cb);
        }
    }
    attn_prefetch(sm_, 0, n, kb0, seg, tid, segk);
    __syncthreads();

    uint32_t qf[5][4];
    {
        uint32_t base_q = sb0 + STG + (uint32_t)(wr + (lane & 15)) * KVSB + ((lane >> 4) * 8) * 2;
        #pragma unroll
        for (int ks = 0; ks < 5; ks++)
            ldsm_x4(qf[ks], base_q + ks * 32);
    }
    __syncthreads();

    float OC[10][4];
    #pragma unroll
    for (int i = 0; i < 10; i++) { OC[i][0] = OC[i][1] = OC[i][2] = OC[i][3] = 0.f; }
    float m0 = -1e30f, m1 = -1e30f, l0 = 0.f, l1 = 0.f;
    const float scale = 0.11180339887498949f;

    for (int t = 0; t < n_tiles; t++) {
        if (t + 1 < n_tiles) attn_prefetch(sm_, (t + 1) & 1, n, kb0 + (t + 1) * 32, seg, tid, segk);
        const uint32_t sb = sb0 + (t & 1) * STG;
        const int* sgk = segk + (t & 1) * 32;

        float SC[4][4];
        #pragma unroll
        for (int g = 0; g < 4; g++) SC[g][0] = SC[g][1] = SC[g][2] = SC[g][3] = 0.f;

        const int krow = ((lane & 16) >> 1) + (lane & 7);
        #pragma unroll
        for (int ks = 0; ks < 5; ks++) {
            const int dimb = (ks * 16 + ((lane >> 3) & 1) * 8) * 2;
            #pragma unroll
            for (int gp = 0; gp < 2; gp++) {
                uint32_t kh[4];
                uint32_t a = sb + (uint32_t)(16 * gp + krow) * KVSB + dimb;
                ldsm_x4(kh, a);
                mma_f16(SC[2*gp+0], qf[ks], kh + 0);
                mma_f16(SC[2*gp+1], qf[ks], kh + 2);
            }
        }

        float sM[4][4];
        #pragma unroll
        for (int g = 0; g < 4; g++) {
            int k0i = 8 * g + 2 * (lane & 3);
            int sA = sgk[k0i], sB = sgk[k0i + 1];
            sM[g][0] = (sA == myseg0) ? SC[g][0] * scale : -1e30f;
            sM[g][1] = (sB == myseg0) ? SC[g][1] * scale : -1e30f;
            sM[g][2] = (sA == myseg1) ? SC[g][2] * scale : -1e30f;
            sM[g][3] = (sB == myseg1) ? SC[g][3] * scale : -1e30f;
        }
        float cm0 = -1e30f, cm1 = -1e30f;
        #pragma unroll
        for (int g = 0; g < 4; g++) {
            cm0 = fmaxf(cm0, fmaxf(sM[g][0], sM[g][1]));
            cm1 = fmaxf(cm1, fmaxf(sM[g][2], sM[g][3]));
        }
        cm0 = fmaxf(cm0, __shfl_xor_sync(0xffffffffu, cm0, 1));
        cm0 = fmaxf(cm0, __shfl_xor_sync(0xffffffffu, cm0, 2));
        cm1 = fmaxf(cm1, __shfl_xor_sync(0xffffffffu, cm1, 1));
        cm1 = fmaxf(cm1, __shfl_xor_sync(0xffffffffu, cm1, 2));
        float nm0 = fmaxf(m0, cm0), nm1 = fmaxf(m1, cm1);
        float f0 = __expf(m0 - nm0), f1 = __expf(m1 - nm1);
        m0 = nm0; m1 = nm1;
        l0 *= f0; l1 *= f1;
        #pragma unroll
        for (int i = 0; i < 10; i++) {
            OC[i][0] *= f0; OC[i][1] *= f0; OC[i][2] *= f1; OC[i][3] *= f1;
        }

        float p[4][4];
        #pragma unroll
        for (int g = 0; g < 4; g++) {
            p[g][0] = __expf(sM[g][0] - m0); p[g][1] = __expf(sM[g][1] - m0);
            p[g][2] = __expf(sM[g][2] - m1); p[g][3] = __expf(sM[g][3] - m1);
            l0 += p[g][0] + p[g][1];
            l1 += p[g][2] + p[g][3];
        }

        uint32_t pa[2][4];
        #pragma unroll
        for (int ks2 = 0; ks2 < 2; ks2++) {
            #pragma unroll
            for (int pos = 0; pos < 4; pos++) {
                int g = 2 * ks2 + (pos >> 1);
                int e = (pos & 1) * 2;
                pa[ks2][pos] = packh(p[g][e], p[g][e + 1]);
            }
        }

        #pragma unroll
        for (int ks2 = 0; ks2 < 2; ks2++) {
            const int vkey = 16 * ks2 + (lane & 15);
            const int vhalf = ((lane >> 4) & 1) * 16;
            #pragma unroll
            for (int dp = 0; dp < 5; dp++) {
                uint32_t vh[4];
                uint32_t a = sb + 5632 + (uint32_t)vkey * KVSB + dp * 32 + vhalf;
                ldsm_x4_t(vh, a);
                mma_f16(OC[2*dp],     pa[ks2], vh + 0);
                mma_f16(OC[2*dp + 1], pa[ks2], vh + 2);
            }
        }
        __syncthreads();
    }

    // epilogue: normalize, single fp16 att output
    l0 += __shfl_xor_sync(0xffffffffu, l0, 1);
    l0 += __shfl_xor_sync(0xffffffffu, l0, 2);
    l1 += __shfl_xor_sync(0xffffffffu, l1, 1);
    l1 += __shfl_xor_sync(0xffffffffu, l1, 2);
    float inv0 = 1.f / l0, inv1 = 1.f / l1;
    const int row0 = q0 + wr + (lane >> 2);
    const int colb = n * HD + 2 * (lane & 3);
    #pragma unroll
    for (int ng = 0; ng < 10; ng++) {
        int col = colb + 8 * ng;
        *(uint32_t*)(g_att16 + (size_t)row0 * HID + col) =
            packh(OC[ng][0] * inv0, OC[ng][1] * inv0);
        *(uint32_t*)(g_att16 + (size_t)(row0 + 8) * HID + col) =
            packh(OC[ng][2] * inv1, OC[ng][3] * inv1);
    }
}

// ---------------------------------------------------------------------------
extern "C" void kernel_launch(void* const* d_in, const int* in_sizes, int n_in,
                              void* d_out, int out_size)
{
    const float* x     = (const float*)d_in[0];
    const float* rope  = (const float*)d_in[1];
    const int*   seg   = (const int*)  d_in[2];
    const float* qkvW  = (const float*)d_in[3];
    const float* qkvB  = (const float*)d_in[4];
    const float* projW = (const float*)d_in[5];
    const float* projB = (const float*)d_in[6];
    float* out = (float*)d_out;

    float* p_qkv;
    cudaGetSymbolAddress((void**)&p_qkv, g_qkv);
    __half *p_xh, *p_xl, *p_wq, *p_wp, *p_att16;
    cudaGetSymbolAddress((void**)&p_xh, g_xh); cudaGetSymbolAddress((void**)&p_xl, g_xl);
    cudaGetSymbolAddress((void**)&p_wq, g_wq); cudaGetSymbolAddress((void**)&p_wp, g_wp);
    cudaGetSymbolAddress((void**)&p_att16, g_att16);

    cudaFuncSetAttribute(gemm_f16_kernel,
                         cudaFuncAttributeMaxDynamicSharedMemorySize, GEMM_SMEM);

    // 0. converts
    convert_splitA_kernel<<<(T*HID + 255)/256, 256>>>(x, p_xh, p_xl, T*HID);
    convertT_kernel<<<dim3(THID/32, HID/32), dim3(32, 8)>>>(qkvW, p_wq, HID, THID);
    convertT_kernel<<<dim3(HID/32, HID/32), dim3(32, 8)>>>(projW, p_wp, HID, HID);

    // 1. qkv = x @ Wqkv + b — single launch; Q,K columns 2-term, V columns 1-term
    gemm_f16_kernel<<<dim3(THID/BN, T/BM), 256, GEMM_SMEM>>>(
        p_xh, p_xl, p_wq, qkvB, p_qkv, THID, HID, 2*HID);

    // 2. RoPE + split into per-head fp16 Q, K, V
    rope_split_kernel<<<(T*NH*HD + 255)/256, 256>>>(rope);

    // 3. Tensor-core block-diagonal flash attention (single fp16)
    attn_mma_kernel<<<dim3(T/64, NH), 128>>>(seg);

    // 4. out = att @ Wproj + b — 1-term (att already fp16-rounded)
    gemm_f16_kernel<<<dim3(HID/BN, T/BM), 256, GEMM_SMEM>>>(
        p_att16, nullptr, p_wp, projB, out, HID, HID, 0);
}

// round 16
// speedup vs baseline: 1.9582x; 1.1877x over previous
#include <cuda_runtime.h>
#include <cuda_fp16.h>
#include <cstdint>
#include <math.h>

#define T 2048
#define HID 1280
#define NH 16
#define HD 80
#define THID (3*HID)

// ---------------- scratch (static device allocations only) ----------------
__device__ float g_qkv[T*THID];

__device__ __half g_x16[T*HID];            // x, single fp16
__device__ __half g_wq[THID*HID];          // Wqkv^T [3840][1280] fp16
__device__ __half g_wp[HID*HID];           // Wproj^T [1280][1280] fp16
__device__ __half g_att16[T*HID];          // attention output, single fp16

// fp16 roped Q, K, V, per head: [head][T][80]
__device__ __half g_q16[NH*T*HD];
__device__ __half g_k16[NH*T*HD];
__device__ __half g_v16[NH*T*HD];

// ---------------- helpers ----------------
__device__ __forceinline__ uint32_t smem_to_u32(const void* p) {
    uint32_t a;
    asm("{ .reg .u64 tmp; cvta.to.shared.u64 tmp, %1; cvt.u32.u64 %0, tmp; }"
        : "=r"(a) : "l"(p));
    return a;
}
__device__ __forceinline__ void mma_f16(float* c, const uint32_t* a, const uint32_t* b) {
    asm volatile("mma.sync.aligned.m16n8k16.row.col.f32.f16.f16.f32 "
        "{%0,%1,%2,%3}, {%4,%5,%6,%7}, {%8,%9}, {%0,%1,%2,%3};"
        : "+f"(c[0]), "+f"(c[1]), "+f"(c[2]), "+f"(c[3])
        : "r"(a[0]), "r"(a[1]), "r"(a[2]), "r"(a[3]), "r"(b[0]), "r"(b[1]));
}
__device__ __forceinline__ void ldsm_x4(uint32_t* r, uint32_t addr) {
    asm volatile("ldmatrix.sync.aligned.m8n8.x4.shared.b16 {%0,%1,%2,%3}, [%4];"
        : "=r"(r[0]), "=r"(r[1]), "=r"(r[2]), "=r"(r[3]) : "r"(addr));
}
__device__ __forceinline__ void ldsm_x4_t(uint32_t* r, uint32_t addr) {
    asm volatile("ldmatrix.sync.aligned.m8n8.x4.trans.shared.b16 {%0,%1,%2,%3}, [%4];"
        : "=r"(r[0]), "=r"(r[1]), "=r"(r[2]), "=r"(r[3]) : "r"(addr));
}
__device__ __forceinline__ void cp_async16(uint32_t dst, const void* src) {
    asm volatile("cp.async.cg.shared.global [%0], [%1], 16;" :: "r"(dst), "l"(src));
}
#define CP_COMMIT() asm volatile("cp.async.commit_group;" ::: "memory")
#define CP_WAIT1()  asm volatile("cp.async.wait_group 1;" ::: "memory")
__device__ __forceinline__ uint32_t packh(float lo_, float hi_) {
    uint32_t r;
    asm("cvt.rn.f16x2.f32 %0, %1, %2;" : "=r"(r) : "f"(hi_), "f"(lo_));
    return r;
}

// ---------------------------------------------------------------------------
// fp32 -> single fp16 convert (x)
// ---------------------------------------------------------------------------
__global__ void convertA_kernel(const float* __restrict__ src,
                                __half* __restrict__ h, int n)
{
    int i = blockIdx.x * blockDim.x + threadIdx.x;
    if (i >= n) return;
    h[i] = __float2half_rn(src[i]);
}

// Transpose [K][N] -> [N][K], single fp16 (GEMM B operand)
__global__ void convertT_kernel(const float* __restrict__ src,
                                __half* __restrict__ h,
                                int K, int N)
{
    __shared__ float t[32][33];
    int nb = blockIdx.x * 32, kb = blockIdx.y * 32;
    int tx = threadIdx.x, ty = threadIdx.y;   // (32, 8)
    #pragma unroll
    for (int j = 0; j < 4; j++)
        t[ty + j * 8][tx] = src[(size_t)(kb + ty + j * 8) * N + nb + tx];
    __syncthreads();
    #pragma unroll
    for (int j = 0; j < 4; j++)
        h[(size_t)(nb + ty + j * 8) * K + kb + tx] = __float2half_rn(t[tx][ty + j * 8]);
}

// ---------------------------------------------------------------------------
// Single-fp16 tensor-core GEMM: C = A @ B^T + bias.
// Round-9 pipeline config (BM=64, 2-stage, 3 CTA/SM). 2 MMAs per g-group.
// ---------------------------------------------------------------------------
#define BM 64
#define BN 128
#define BK 32
#define ASTRIDE 40
#define A_TILE (64*80)                   // 5120 B
#define B_TILE (128*80)                  // 10240 B
#define STAGE_B (A_TILE + B_TILE)        // 15360 B
#define GEMM_SMEM (2*STAGE_B)            // 30720 B

__global__ __launch_bounds__(256, 3)
void gemm_f16_kernel(const __half* __restrict__ A,
                     const __half* __restrict__ Bh,
                     const float* __restrict__ bias,
                     float* __restrict__ C,
                     int ldC, int K)
{
    extern __shared__ char sm[];
    const uint32_t sbase = smem_to_u32(sm);

    const int tid  = threadIdx.x;
    const int wid  = tid >> 5;
    const int lane = tid & 31;
    const int m0 = blockIdx.y * BM, n0 = blockIdx.x * BN;
    const int wm = (wid >> 1) * 16;
    const int wn = (wid & 1) * 64;

    float acc[8][4];
    #pragma unroll
    for (int b = 0; b < 8; b++)
        #pragma unroll
        for (int c = 0; c < 4; c++) acc[b][c] = 0.f;

    const int c_row = tid >> 2;
    const int c_col = (tid & 3) * 8;
    const uint32_t s_off  = (uint32_t)(c_row * ASTRIDE + c_col) * 2;
    const uint32_t s_off2 = s_off + (uint32_t)64 * ASTRIDE * 2;

    const __half* gA  = A  + (size_t)(m0 + c_row) * K + c_col;
    const __half* gBh = Bh + (size_t)(n0 + c_row) * K + c_col;
    const size_t g2 = (size_t)64 * K;

    const int niter = K / BK;

    {
        uint32_t sb = sbase;
        cp_async16(sb + s_off,            gA);
        cp_async16(sb + A_TILE + s_off,   gBh);
        cp_async16(sb + A_TILE + s_off2,  gBh + g2);
    }
    CP_COMMIT();

    const int a_row  = (lane & 15);
    const int a_colb = (lane >> 4) * 16;
    const int b_row  = (lane & 7) + ((lane >> 4) << 3);
    const int b_colb = (((lane >> 3) & 1)) * 16;

    for (int it = 0; it < niter; it++) {
        int nk = it + 1;
        if (nk < niter) {
            uint32_t sb = sbase + (nk & 1) * STAGE_B;
            int k0 = nk * BK;
            cp_async16(sb + s_off,            gA + k0);
            cp_async16(sb + A_TILE + s_off,   gBh + k0);
            cp_async16(sb + A_TILE + s_off2,  gBh + g2 + k0);
        }
        CP_COMMIT();
        CP_WAIT1();
        __syncthreads();

        const uint32_t sb  = sbase + (it & 1) * STAGE_B;
        const uint32_t sA  = sb;
        const uint32_t sBh = sb + A_TILE;

        #pragma unroll
        for (int k16 = 0; k16 < 2; k16++) {
            const int kcb = k16 * 32;
            uint32_t ah[4];
            {
                uint32_t ro = (uint32_t)(wm + a_row) * 80 + kcb + a_colb;
                ldsm_x4(ah, sA + ro);
            }
            #pragma unroll
            for (int g = 0; g < 4; g++) {
                uint32_t ro = (uint32_t)(wn + g*16 + b_row) * 80 + kcb + b_colb;
                uint32_t bh[4];
                ldsm_x4(bh, sBh + ro);
                mma_f16(acc[g*2+0], ah, bh + 0);
                mma_f16(acc[g*2+1], ah, bh + 2);
            }
        }
        __syncthreads();
    }

    {
        int r0 = m0 + wm + (lane >> 2);
        #pragma unroll
        for (int t = 0; t < 8; t++) {
            int col = n0 + wn + t*8 + (lane & 3)*2;
            float b0 = bias[col], b1 = bias[col + 1];
            float2 v0 = { acc[t][0] + b0, acc[t][1] + b1 };
            float2 v1 = { acc[t][2] + b0, acc[t][3] + b1 };
            *(float2*)(C + (size_t)r0 * ldC + col)       = v0;
            *(float2*)(C + (size_t)(r0 + 8) * ldC + col) = v1;
        }
    }
}

// ---------------------------------------------------------------------------
// RoPE + split qkv into per-head fp16 Q, K, V buffers [head][T][80].
// ---------------------------------------------------------------------------
__global__ void rope_split_kernel(const float* __restrict__ rope)
{
    int idx = blockIdx.x * blockDim.x + threadIdx.x;
    if (idx >= T * NH * HD) return;
    int d = idx % HD;
    int n = (idx / HD) % NH;
    int t = idx / (HD * NH);

    int dr = (d < 40) ? d : d - 40;
    float ang = rope[t * 40 + dr];
    float c = cosf(ang), s = sinf(ang);

    const float* qrow = g_qkv + (size_t)t * THID + n * HD;
    float qv, kv;
    if (d < 40) {
        qv = qrow[d] * c        - qrow[d + 40] * s;
        kv = qrow[HID + d] * c  - qrow[HID + d + 40] * s;
    } else {
        qv = qrow[d - 40] * s       + qrow[d] * c;
        kv = qrow[HID + d - 40] * s + qrow[HID + d] * c;
    }
    float vv = qrow[2 * HID + d];
    int o = (n * T + t) * HD + d;
    g_q16[o] = __float2half_rn(qv);
    g_k16[o] = __float2half_rn(kv);
    g_v16[o] = __float2half_rn(vv);
}

// ---------------------------------------------------------------------------
// Tensor-core flash attention (single fp16, 40 MMAs/tile) — proven round 14/15.
// ---------------------------------------------------------------------------
#define KVSB 176
#define STG  11264

__device__ __forceinline__ void attn_prefetch(char* sm_, int sbuf, int n, int kb,
                                              const int* __restrict__ seg,
                                              int tid, int* segk)
{
    char* dst = sm_ + sbuf * STG;
    #pragma unroll
    for (int i = 0; i < 5; i++) {
        int c = tid + i * 128;
        int arr = c / 320, w = c % 320;    // 0=K, 1=V
        int key = w / 10, cb = (w % 10) * 16;
        int kg = kb + key;
        uint4 v = make_uint4(0u, 0u, 0u, 0u);
        const __half* base = (arr == 0) ? g_k16 : g_v16;
        if (kg < T)
            v = *(const uint4*)((const char*)(base + (size_t)(n * T + kg) * HD) + cb);
        *(uint4*)(dst + arr * 5632 + key * KVSB + cb) = v;
    }
    if (tid < 32) segk[sbuf * 32 + tid] = (kb + tid < T) ? seg[kb + tid] : -1;
}

__global__ __launch_bounds__(128)
void attn_mma_kernel(const int* __restrict__ seg)
{
    __shared__ __align__(16) char sm_[2 * STG + 256];
    int* segk = (int*)(sm_ + 2 * STG);
    const uint32_t sb0 = smem_to_u32(sm_);

    const int n = blockIdx.y;
    const int q0 = blockIdx.x * 64;
    const int tid = threadIdx.x;
    const int lane = tid & 31;
    const int wid = tid >> 5;
    const int wr = wid * 16;

    const int seg_lo = seg[q0], seg_hi = seg[q0 + 63];
    int lo = 0, hi = T;
    while (lo < hi) { int mid = (lo + hi) >> 1; if (seg[mid] < seg_lo) lo = mid + 1; else hi = mid; }
    const int kstart = lo;
    hi = T;
    while (lo < hi) { int mid = (lo + hi) >> 1; if (seg[mid] <= seg_hi) lo = mid + 1; else hi = mid; }
    const int kend = lo;
    const int kb0 = kstart & ~31;
    const int n_tiles = (kend - kb0 + 31) >> 5;

    const int myseg0 = seg[q0 + wr + (lane >> 2)];
    const int myseg1 = seg[q0 + wr + (lane >> 2) + 8];

    {
        const char* gq = (const char*)(g_q16 + (size_t)(n * T + q0) * HD);
        #pragma unroll
        for (int i = 0; i < 5; i++) {
            int c = tid + i * 128;
            int row = c / 10, cb = (c % 10) * 16;
            *(uint4*)(sm_ + STG + row * KVSB + cb) = *(const uint4*)(gq + row * 160 + cb);
        }
    }
    attn_prefetch(sm_, 0, n, kb0, seg, tid, segk);
    __syncthreads();

    uint32_t qf[5][4];
    {
        uint32_t base_q = sb0 + STG + (uint32_t)(wr + (lane & 15)) * KVSB + ((lane >> 4) * 8) * 2;
        #pragma unroll
        for (int ks = 0; ks < 5; ks++)
            ldsm_x4(qf[ks], base_q + ks * 32);
    }
    __syncthreads();

    float OC[10][4];
    #pragma unroll
    for (int i = 0; i < 10; i++) { OC[i][0] = OC[i][1] = OC[i][2] = OC[i][3] = 0.f; }
    float m0 = -1e30f, m1 = -1e30f, l0 = 0.f, l1 = 0.f;
    const float scale = 0.11180339887498949f;

    for (int t = 0; t < n_tiles; t++) {
        if (t + 1 < n_tiles) attn_prefetch(sm_, (t + 1) & 1, n, kb0 + (t + 1) * 32, seg, tid, segk);
        const uint32_t sb = sb0 + (t & 1) * STG;
        const int* sgk = segk + (t & 1) * 32;

        float SC[4][4];
        #pragma unroll
        for (int g = 0; g < 4; g++) SC[g][0] = SC[g][1] = SC[g][2] = SC[g][3] = 0.f;

        const int krow = ((lane & 16) >> 1) + (lane & 7);
        #pragma unroll
        for (int ks = 0; ks < 5; ks++) {
            const int dimb = (ks * 16 + ((lane >> 3) & 1) * 8) * 2;
            #pragma unroll
            for (int gp = 0; gp < 2; gp++) {
                uint32_t kh[4];
                uint32_t a = sb + (uint32_t)(16 * gp + krow) * KVSB + dimb;
                ldsm_x4(kh, a);
                mma_f16(SC[2*gp+0], qf[ks], kh + 0);
                mma_f16(SC[2*gp+1], qf[ks], kh + 2);
            }
        }

        float sM[4][4];
        #pragma unroll
        for (int g = 0; g < 4; g++) {
            int k0i = 8 * g + 2 * (lane & 3);
            int sA = sgk[k0i], sB = sgk[k0i + 1];
            sM[g][0] = (sA == myseg0) ? SC[g][0] * scale : -1e30f;
            sM[g][1] = (sB == myseg0) ? SC[g][1] * scale : -1e30f;
            sM[g][2] = (sA == myseg1) ? SC[g][2] * scale : -1e30f;
            sM[g][3] = (sB == myseg1) ? SC[g][3] * scale : -1e30f;
        }
        float cm0 = -1e30f, cm1 = -1e30f;
        #pragma unroll
        for (int g = 0; g < 4; g++) {
            cm0 = fmaxf(cm0, fmaxf(sM[g][0], sM[g][1]));
            cm1 = fmaxf(cm1, fmaxf(sM[g][2], sM[g][3]));
        }
        cm0 = fmaxf(cm0, __shfl_xor_sync(0xffffffffu, cm0, 1));
        cm0 = fmaxf(cm0, __shfl_xor_sync(0xffffffffu, cm0, 2));
        cm1 = fmaxf(cm1, __shfl_xor_sync(0xffffffffu, cm1, 1));
        cm1 = fmaxf(cm1, __shfl_xor_sync(0xffffffffu, cm1, 2));
        float nm0 = fmaxf(m0, cm0), nm1 = fmaxf(m1, cm1);
        float f0 = __expf(m0 - nm0), f1 = __expf(m1 - nm1);
        m0 = nm0; m1 = nm1;
        l0 *= f0; l1 *= f1;
        #pragma unroll
        for (int i = 0; i < 10; i++) {
            OC[i][0] *= f0; OC[i][1] *= f0; OC[i][2] *= f1; OC[i][3] *= f1;
        }

        float p[4][4];
        #pragma unroll
        for (int g = 0; g < 4; g++) {
            p[g][0] = __expf(sM[g][0] - m0); p[g][1] = __expf(sM[g][1] - m0);
            p[g][2] = __expf(sM[g][2] - m1); p[g][3] = __expf(sM[g][3] - m1);
            l0 += p[g][0] + p[g][1];
            l1 += p[g][2] + p[g][3];
        }

        uint32_t pa[2][4];
        #pragma unroll
        for (int ks2 = 0; ks2 < 2; ks2++) {
            #pragma unroll
            for (int pos = 0; pos < 4; pos++) {
                int g = 2 * ks2 + (pos >> 1);
                int e = (pos & 1) * 2;
                pa[ks2][pos] = packh(p[g][e], p[g][e + 1]);
            }
        }

        #pragma unroll
        for (int ks2 = 0; ks2 < 2; ks2++) {
            const int vkey = 16 * ks2 + (lane & 15);
            const int vhalf = ((lane >> 4) & 1) * 16;
            #pragma unroll
            for (int dp = 0; dp < 5; dp++) {
                uint32_t vh[4];
                uint32_t a = sb + 5632 + (uint32_t)vkey * KVSB + dp * 32 + vhalf;
                ldsm_x4_t(vh, a);
                mma_f16(OC[2*dp],     pa[ks2], vh + 0);
                mma_f16(OC[2*dp + 1], pa[ks2], vh + 2);
            }
        }
        __syncthreads();
    }

    l0 += __shfl_xor_sync(0xffffffffu, l0, 1);
    l0 += __shfl_xor_sync(0xffffffffu, l0, 2);
    l1 += __shfl_xor_sync(0xffffffffu, l1, 1);
    l1 += __shfl_xor_sync(0xffffffffu, l1, 2);
    float inv0 = 1.f / l0, inv1 = 1.f / l1;
    const int row0 = q0 + wr + (lane >> 2);
    const int colb = n * HD + 2 * (lane & 3);
    #pragma unroll
    for (int ng = 0; ng < 10; ng++) {
        int col = colb + 8 * ng;
        *(uint32_t*)(g_att16 + (size_t)row0 * HID + col) =
            packh(OC[ng][0] * inv0, OC[ng][1] * inv0);
        *(uint32_t*)(g_att16 + (size_t)(row0 + 8) * HID + col) =
            packh(OC[ng][2] * inv1, OC[ng][3] * inv1);
    }
}

// ---------------------------------------------------------------------------
extern "C" void kernel_launch(void* const* d_in, const int* in_sizes, int n_in,
                              void* d_out, int out_size)
{
    const float* x     = (const float*)d_in[0];
    const float* rope  = (const float*)d_in[1];
    const int*   seg   = (const int*)  d_in[2];
    const float* qkvW  = (const float*)d_in[3];
    const float* qkvB  = (const float*)d_in[4];
    const float* projW = (const float*)d_in[5];
    const float* projB = (const float*)d_in[6];
    float* out = (float*)d_out;

    float* p_qkv;
    cudaGetSymbolAddress((void**)&p_qkv, g_qkv);
    __half *p_x16, *p_wq, *p_wp, *p_att16;
    cudaGetSymbolAddress((void**)&p_x16, g_x16);
    cudaGetSymbolAddress((void**)&p_wq, g_wq); cudaGetSymbolAddress((void**)&p_wp, g_wp);
    cudaGetSymbolAddress((void**)&p_att16, g_att16);

    cudaFuncSetAttribute(gemm_f16_kernel,
                         cudaFuncAttributeMaxDynamicSharedMemorySize, GEMM_SMEM);

    // 0. converts (all single fp16 now)
    convertA_kernel<<<(T*HID + 255)/256, 256>>>(x, p_x16, T*HID);
    convertT_kernel<<<dim3(THID/32, HID/32), dim3(32, 8)>>>(qkvW, p_wq, HID, THID);
    convertT_kernel<<<dim3(HID/32, HID/32), dim3(32, 8)>>>(projW, p_wp, HID, HID);

    // 1. qkv = x @ Wqkv + b  (single fp16)
    gemm_f16_kernel<<<dim3(THID/BN, T/BM), 256, GEMM_SMEM>>>(
        p_x16, p_wq, qkvB, p_qkv, THID, HID);

    // 2. RoPE + split into per-head fp16 Q, K, V
    rope_split_kernel<<<(T*NH*HD + 255)/256, 256>>>(rope);

    // 3. Tensor-core block-diagonal flash attention (single fp16)
    attn_mma_kernel<<<dim3(T/64, NH), 128>>>(seg);

    // 4. out = att @ Wproj + b  (single fp16)
    gemm_f16_kernel<<<dim3(HID/BN, T/BM), 256, GEMM_SMEM>>>(
        p_att16, p_wp, projB, out, HID, HID);
}

// round 17
// speedup vs baseline: 2.1790x; 1.1128x over previous
#include <cuda_runtime.h>
#include <cuda_fp16.h>
#include <cstdint>
#include <math.h>

#define T 2048
#define HID 1280
#define NH 16
#define HD 80
#define THID (3*HID)

// ---------------- scratch (static device allocations only) ----------------
__device__ float g_qkv[T*THID];

__device__ __half g_x16[T*HID];            // x, single fp16
__device__ __half g_wq[THID*HID];          // Wqkv^T [3840][1280] fp16
__device__ __half g_wp[HID*HID];           // Wproj^T [1280][1280] fp16
__device__ __half g_att16[T*HID];          // attention output, single fp16

// fp16 roped Q, K, V, per head: [head][T][80]
__device__ __half g_q16[NH*T*HD];
__device__ __half g_k16[NH*T*HD];
__device__ __half g_v16[NH*T*HD];

// ---------------- helpers ----------------
__device__ __forceinline__ uint32_t smem_to_u32(const void* p) {
    uint32_t a;
    asm("{ .reg .u64 tmp; cvta.to.shared.u64 tmp, %1; cvt.u32.u64 %0, tmp; }"
        : "=r"(a) : "l"(p));
    return a;
}
__device__ __forceinline__ void mma_f16(float* c, const uint32_t* a, const uint32_t* b) {
    asm volatile("mma.sync.aligned.m16n8k16.row.col.f32.f16.f16.f32 "
        "{%0,%1,%2,%3}, {%4,%5,%6,%7}, {%8,%9}, {%0,%1,%2,%3};"
        : "+f"(c[0]), "+f"(c[1]), "+f"(c[2]), "+f"(c[3])
        : "r"(a[0]), "r"(a[1]), "r"(a[2]), "r"(a[3]), "r"(b[0]), "r"(b[1]));
}
__device__ __forceinline__ void ldsm_x4(uint32_t* r, uint32_t addr) {
    asm volatile("ldmatrix.sync.aligned.m8n8.x4.shared.b16 {%0,%1,%2,%3}, [%4];"
        : "=r"(r[0]), "=r"(r[1]), "=r"(r[2]), "=r"(r[3]) : "r"(addr));
}
__device__ __forceinline__ void ldsm_x4_t(uint32_t* r, uint32_t addr) {
    asm volatile("ldmatrix.sync.aligned.m8n8.x4.trans.shared.b16 {%0,%1,%2,%3}, [%4];"
        : "=r"(r[0]), "=r"(r[1]), "=r"(r[2]), "=r"(r[3]) : "r"(addr));
}
__device__ __forceinline__ void cp_async16(uint32_t dst, const void* src) {
    asm volatile("cp.async.cg.shared.global [%0], [%1], 16;" :: "r"(dst), "l"(src));
}
#define CP_COMMIT() asm volatile("cp.async.commit_group;" ::: "memory")
#define CP_WAIT1()  asm volatile("cp.async.wait_group 1;" ::: "memory")
__device__ __forceinline__ uint32_t packh(float lo_, float hi_) {
    uint32_t r;
    asm("cvt.rn.f16x2.f32 %0, %1, %2;" : "=r"(r) : "f"(hi_), "f"(lo_));
    return r;
}

// ---------------------------------------------------------------------------
// fp32 -> single fp16 convert (x)
// ---------------------------------------------------------------------------
__global__ void convertA_kernel(const float* __restrict__ src,
                                __half* __restrict__ h, int n)
{
    int i = blockIdx.x * blockDim.x + threadIdx.x;
    if (i >= n) return;
    h[i] = __float2half_rn(src[i]);
}

// Transpose [K][N] -> [N][K], single fp16 (GEMM B operand)
__global__ void convertT_kernel(const float* __restrict__ src,
                                __half* __restrict__ h,
                                int K, int N)
{
    __shared__ float t[32][33];
    int nb = blockIdx.x * 32, kb = blockIdx.y * 32;
    int tx = threadIdx.x, ty = threadIdx.y;   // (32, 8)
    #pragma unroll
    for (int j = 0; j < 4; j++)
        t[ty + j * 8][tx] = src[(size_t)(kb + ty + j * 8) * N + nb + tx];
    __syncthreads();
    #pragma unroll
    for (int j = 0; j < 4; j++)
        h[(size_t)(nb + ty + j * 8) * K + kb + tx] = __float2half_rn(t[tx][ty + j * 8]);
}

// ---------------------------------------------------------------------------
// Single-fp16 tensor-core GEMM: C = A @ B^T + bias.
// Round 17: BK=64 (20 K-iters instead of 40) — halves per-iter barrier/wait
// overhead. Row stride 144B (conflict-free: 9r mod 8 distinct). 2 stages,
// 3 CTA/SM retained.
// ---------------------------------------------------------------------------
#define BM 64
#define BN 128
#define BK 64
#define RSTRIDE 144                      // bytes per smem row (128B data + 16 pad)
#define A_TILE (64*RSTRIDE)              // 9216 B
#define B_TILE (128*RSTRIDE)             // 18432 B
#define STAGE_B (A_TILE + B_TILE)        // 27648 B
#define GEMM_SMEM (2*STAGE_B)            // 55296 B

__global__ __launch_bounds__(256, 3)
void gemm_f16_kernel(const __half* __restrict__ A,
                     const __half* __restrict__ Bh,
                     const float* __restrict__ bias,
                     float* __restrict__ C,
                     int ldC, int K)
{
    extern __shared__ char sm[];
    const uint32_t sbase = smem_to_u32(sm);

    const int tid  = threadIdx.x;
    const int wid  = tid >> 5;
    const int lane = tid & 31;
    const int m0 = blockIdx.y * BM, n0 = blockIdx.x * BN;
    const int wm = (wid >> 1) * 16;
    const int wn = (wid & 1) * 64;

    float acc[8][4];
    #pragma unroll
    for (int b = 0; b < 8; b++)
        #pragma unroll
        for (int c = 0; c < 4; c++) acc[b][c] = 0.f;

    // cp.async mapping: 1536 chunks of 16B per stage (A 512, B 1024), 6/thread
    const __half* gp[6];
    uint32_t sd[6];
    #pragma unroll
    for (int i = 0; i < 6; i++) {
        int c = tid + i * 256;
        if (c < 512) {
            int row = c >> 3, cb = (c & 7) * 16;
            gp[i] = A + (size_t)(m0 + row) * K + (cb >> 1);
            sd[i] = (uint32_t)(row * RSTRIDE + cb);
        } else {
            int c2 = c - 512;
            int row = c2 >> 3, cb = (c2 & 7) * 16;
            gp[i] = Bh + (size_t)(n0 + row) * K + (cb >> 1);
            sd[i] = (uint32_t)(A_TILE + row * RSTRIDE + cb);
        }
    }

    const int niter = K / BK;   // 20

    // prologue: stage 0
    #pragma unroll
    for (int i = 0; i < 6; i++) cp_async16(sbase + sd[i], gp[i]);
    CP_COMMIT();

    const int a_row  = (lane & 15);
    const int a_colb = (lane >> 4) * 16;
    const int b_row  = (lane & 7) + ((lane >> 4) << 3);
    const int b_colb = (((lane >> 3) & 1)) * 16;

    for (int it = 0; it < niter; it++) {
        int nk = it + 1;
        if (nk < niter) {
            uint32_t sb = sbase + (nk & 1) * STAGE_B;
            int k0 = nk * BK;
            #pragma unroll
            for (int i = 0; i < 6; i++) cp_async16(sb + sd[i], gp[i] + k0);
        }
        CP_COMMIT();
        CP_WAIT1();
        __syncthreads();

        const uint32_t sb  = sbase + (it & 1) * STAGE_B;
        const uint32_t sA  = sb;
        const uint32_t sBh = sb + A_TILE;

        #pragma unroll
        for (int ks = 0; ks < 4; ks++) {
            const int kcb = ks * 32;
            uint32_t ah[4];
            {
                uint32_t ro = (uint32_t)(wm + a_row) * RSTRIDE + kcb + a_colb;
                ldsm_x4(ah, sA + ro);
            }
            #pragma unroll
            for (int g = 0; g < 4; g++) {
                uint32_t ro = (uint32_t)(wn + g*16 + b_row) * RSTRIDE + kcb + b_colb;
                uint32_t bh[4];
                ldsm_x4(bh, sBh + ro);
                mma_f16(acc[g*2+0], ah, bh + 0);
                mma_f16(acc[g*2+1], ah, bh + 2);
            }
        }
        __syncthreads();
    }

    {
        int r0 = m0 + wm + (lane >> 2);
        #pragma unroll
        for (int t = 0; t < 8; t++) {
            int col = n0 + wn + t*8 + (lane & 3)*2;
            float b0 = bias[col], b1 = bias[col + 1];
            float2 v0 = { acc[t][0] + b0, acc[t][1] + b1 };
            float2 v1 = { acc[t][2] + b0, acc[t][3] + b1 };
            *(float2*)(C + (size_t)r0 * ldC + col)       = v0;
            *(float2*)(C + (size_t)(r0 + 8) * ldC + col) = v1;
        }
    }
}

// ---------------------------------------------------------------------------
// RoPE + split qkv into per-head fp16 Q, K, V buffers [head][T][80].
// ---------------------------------------------------------------------------
__global__ void rope_split_kernel(const float* __restrict__ rope)
{
    int idx = blockIdx.x * blockDim.x + threadIdx.x;
    if (idx >= T * NH * HD) return;
    int d = idx % HD;
    int n = (idx / HD) % NH;
    int t = idx / (HD * NH);

    int dr = (d < 40) ? d : d - 40;
    float ang = rope[t * 40 + dr];
    float c = cosf(ang), s = sinf(ang);

    const float* qrow = g_qkv + (size_t)t * THID + n * HD;
    float qv, kv;
    if (d < 40) {
        qv = qrow[d] * c        - qrow[d + 40] * s;
        kv = qrow[HID + d] * c  - qrow[HID + d + 40] * s;
    } else {
        qv = qrow[d - 40] * s       + qrow[d] * c;
        kv = qrow[HID + d - 40] * s + qrow[HID + d] * c;
    }
    float vv = qrow[2 * HID + d];
    int o = (n * T + t) * HD + d;
    g_q16[o] = __float2half_rn(qv);
    g_k16[o] = __float2half_rn(kv);
    g_v16[o] = __float2half_rn(vv);
}

// ---------------------------------------------------------------------------
// Tensor-core flash attention (single fp16, 40 MMAs/tile) — proven config.
// ---------------------------------------------------------------------------
#define KVSB 176
#define STG  11264

__device__ __forceinline__ void attn_prefetch(char* sm_, int sbuf, int n, int kb,
                                              const int* __restrict__ seg,
                                              int tid, int* segk)
{
    char* dst = sm_ + sbuf * STG;
    #pragma unroll
    for (int i = 0; i < 5; i++) {
        int c = tid + i * 128;
        int arr = c / 320, w = c % 320;    // 0=K, 1=V
        int key = w / 10, cb = (w % 10) * 16;
        int kg = kb + key;
        uint4 v = make_uint4(0u, 0u, 0u, 0u);
        const __half* base = (arr == 0) ? g_k16 : g_v16;
        if (kg < T)
            v = *(const uint4*)((const char*)(base + (size_t)(n * T + kg) * HD) + cb);
        *(uint4*)(dst + arr * 5632 + key * KVSB + cb) = v;
    }
    if (tid < 32) segk[sbuf * 32 + tid] = (kb + tid < T) ? seg[kb + tid] : -1;
}

__global__ __launch_bounds__(128)
void attn_mma_kernel(const int* __restrict__ seg)
{
    __shared__ __align__(16) char sm_[2 * STG + 256];
    int* segk = (int*)(sm_ + 2 * STG);
    const uint32_t sb0 = smem_to_u32(sm_);

    const int n = blockIdx.y;
    const int q0 = blockIdx.x * 64;
    const int tid = threadIdx.x;
    const int lane = tid & 31;
    const int wid = tid >> 5;
    const int wr = wid * 16;

    const int seg_lo = seg[q0], seg_hi = seg[q0 + 63];
    int lo = 0, hi = T;
    while (lo < hi) { int mid = (lo + hi) >> 1; if (seg[mid] < seg_lo) lo = mid + 1; else hi = mid; }
    const int kstart = lo;
    hi = T;
    while (lo < hi) { int mid = (lo + hi) >> 1; if (seg[mid] <= seg_hi) lo = mid + 1; else hi = mid; }
    const int kend = lo;
    const int kb0 = kstart & ~31;
    const int n_tiles = (kend - kb0 + 31) >> 5;

    const int myseg0 = seg[q0 + wr + (lane >> 2)];
    const int myseg1 = seg[q0 + wr + (lane >> 2) + 8];

    {
        const char* gq = (const char*)(g_q16 + (size_t)(n * T + q0) * HD);
        #pragma unroll
        for (int i = 0; i < 5; i++) {
            int c = tid + i * 128;
            int row = c / 10, cb = (c % 10) * 16;
            *(uint4*)(sm_ + STG + row * KVSB + cb) = *(const uint4*)(gq + row * 160 + cb);
        }
    }
    attn_prefetch(sm_, 0, n, kb0, seg, tid, segk);
    __syncthreads();

    uint32_t qf[5][4];
    {
        uint32_t base_q = sb0 + STG + (uint32_t)(wr + (lane & 15)) * KVSB + ((lane >> 4) * 8) * 2;
        #pragma unroll
        for (int ks = 0; ks < 5; ks++)
            ldsm_x4(qf[ks], base_q + ks * 32);
    }
    __syncthreads();

    float OC[10][4];
    #pragma unroll
    for (int i = 0; i < 10; i++) { OC[i][0] = OC[i][1] = OC[i][2] = OC[i][3] = 0.f; }
    float m0 = -1e30f, m1 = -1e30f, l0 = 0.f, l1 = 0.f;
    const float scale = 0.11180339887498949f;

    for (int t = 0; t < n_tiles; t++) {
        if (t + 1 < n_tiles) attn_prefetch(sm_, (t + 1) & 1, n, kb0 + (t + 1) * 32, seg, tid, segk);
        const uint32_t sb = sb0 + (t & 1) * STG;
        const int* sgk = segk + (t & 1) * 32;

        float SC[4][4];
        #pragma unroll
        for (int g = 0; g < 4; g++) SC[g][0] = SC[g][1] = SC[g][2] = SC[g][3] = 0.f;

        const int krow = ((lane & 16) >> 1) + (lane & 7);
        #pragma unroll
        for (int ks = 0; ks < 5; ks++) {
            const int dimb = (ks * 16 + ((lane >> 3) & 1) * 8) * 2;
            #pragma unroll
            for (int gp2 = 0; gp2 < 2; gp2++) {
                uint32_t kh[4];
                uint32_t a = sb + (uint32_t)(16 * gp2 + krow) * KVSB + dimb;
                ldsm_x4(kh, a);
                mma_f16(SC[2*gp2+0], qf[ks], kh + 0);
                mma_f16(SC[2*gp2+1], qf[ks], kh + 2);
            }
        }

        float sM[4][4];
        #pragma unroll
        for (int g = 0; g < 4; g++) {
            int k0i = 8 * g + 2 * (lane & 3);
            int sA2 = sgk[k0i], sB2 = sgk[k0i + 1];
            sM[g][0] = (sA2 == myseg0) ? SC[g][0] * scale : -1e30f;
            sM[g][1] = (sB2 == myseg0) ? SC[g][1] * scale : -1e30f;
            sM[g][2] = (sA2 == myseg1) ? SC[g][2] * scale : -1e30f;
            sM[g][3] = (sB2 == myseg1) ? SC[g][3] * scale : -1e30f;
        }
        float cm0 = -1e30f, cm1 = -1e30f;
        #pragma unroll
        for (int g = 0; g < 4; g++) {
            cm0 = fmaxf(cm0, fmaxf(sM[g][0], sM[g][1]));
            cm1 = fmaxf(cm1, fmaxf(sM[g][2], sM[g][3]));
        }
        cm0 = fmaxf(cm0, __shfl_xor_sync(0xffffffffu, cm0, 1));
        cm0 = fmaxf(cm0, __shfl_xor_sync(0xffffffffu, cm0, 2));
        cm1 = fmaxf(cm1, __shfl_xor_sync(0xffffffffu, cm1, 1));
        cm1 = fmaxf(cm1, __shfl_xor_sync(0xffffffffu, cm1, 2));
        float nm0 = fmaxf(m0, cm0), nm1 = fmaxf(m1, cm1);
        float f0 = __expf(m0 - nm0), f1 = __expf(m1 - nm1);
        m0 = nm0; m1 = nm1;
        l0 *= f0; l1 *= f1;
        #pragma unroll
        for (int i = 0; i < 10; i++) {
            OC[i][0] *= f0; OC[i][1] *= f0; OC[i][2] *= f1; OC[i][3] *= f1;
        }

        float p[4][4];
        #pragma unroll
        for (int g = 0; g < 4; g++) {
            p[g][0] = __expf(sM[g][0] - m0); p[g][1] = __expf(sM[g][1] - m0);
            p[g][2] = __expf(sM[g][2] - m1); p[g][3] = __expf(sM[g][3] - m1);
            l0 += p[g][0] + p[g][1];
            l1 += p[g][2] + p[g][3];
        }

        uint32_t pa[2][4];
        #pragma unroll
        for (int ks2 = 0; ks2 < 2; ks2++) {
            #pragma unroll
            for (int pos = 0; pos < 4; pos++) {
                int g = 2 * ks2 + (pos >> 1);
                int e = (pos & 1) * 2;
                pa[ks2][pos] = packh(p[g][e], p[g][e + 1]);
            }
        }

        #pragma unroll
        for (int ks2 = 0; ks2 < 2; ks2++) {
            const int vkey = 16 * ks2 + (lane & 15);
            const int vhalf = ((lane >> 4) & 1) * 16;
            #pragma unroll
            for (int dp = 0; dp < 5; dp++) {
                uint32_t vh[4];
                uint32_t a = sb + 5632 + (uint32_t)vkey * KVSB + dp * 32 + vhalf;
                ldsm_x4_t(vh, a);
                mma_f16(OC[2*dp],     pa[ks2], vh + 0);
                mma_f16(OC[2*dp + 1], pa[ks2], vh + 2);
            }
        }
        __syncthreads();
    }

    l0 += __shfl_xor_sync(0xffffffffu, l0, 1);
    l0 += __shfl_xor_sync(0xffffffffu, l0, 2);
    l1 += __shfl_xor_sync(0xffffffffu, l1, 1);
    l1 += __shfl_xor_sync(0xffffffffu, l1, 2);
    float inv0 = 1.f / l0, inv1 = 1.f / l1;
    const int row0 = q0 + wr + (lane >> 2);
    const int colb = n * HD + 2 * (lane & 3);
    #pragma unroll
    for (int ng = 0; ng < 10; ng++) {
        int col = colb + 8 * ng;
        *(uint32_t*)(g_att16 + (size_t)row0 * HID + col) =
            packh(OC[ng][0] * inv0, OC[ng][1] * inv0);
        *(uint32_t*)(g_att16 + (size_t)(row0 + 8) * HID + col) =
            packh(OC[ng][2] * inv1, OC[ng][3] * inv1);
    }
}

// ---------------------------------------------------------------------------
extern "C" void kernel_launch(void* const* d_in, const int* in_sizes, int n_in,
                              void* d_out, int out_size)
{
    const float* x     = (const float*)d_in[0];
    const float* rope  = (const float*)d_in[1];
    const int*   seg   = (const int*)  d_in[2];
    const float* qkvW  = (const float*)d_in[3];
    const float* qkvB  = (const float*)d_in[4];
    const float* projW = (const float*)d_in[5];
    const float* projB = (const float*)d_in[6];
    float* out = (float*)d_out;

    float* p_qkv;
    cudaGetSymbolAddress((void**)&p_qkv, g_qkv);
    __half *p_x16, *p_wq, *p_wp, *p_att16;
    cudaGetSymbolAddress((void**)&p_x16, g_x16);
    cudaGetSymbolAddress((void**)&p_wq, g_wq); cudaGetSymbolAddress((void**)&p_wp, g_wp);
    cudaGetSymbolAddress((void**)&p_att16, g_att16);

    cudaFuncSetAttribute(gemm_f16_kernel,
                         cudaFuncAttributeMaxDynamicSharedMemorySize, GEMM_SMEM);

    // 0. converts (all single fp16)
    convertA_kernel<<<(T*HID + 255)/256, 256>>>(x, p_x16, T*HID);
    convertT_kernel<<<dim3(THID/32, HID/32), dim3(32, 8)>>>(qkvW, p_wq, HID, THID);
    convertT_kernel<<<dim3(HID/32, HID/32), dim3(32, 8)>>>(projW, p_wp, HID, HID);

    // 1. qkv = x @ Wqkv + b  (fp16, BK=64)
    gemm_f16_kernel<<<dim3(THID/BN, T/BM), 256, GEMM_SMEM>>>(
        p_x16, p_wq, qkvB, p_qkv, THID, HID);

    // 2. RoPE + split into per-head fp16 Q, K, V
    rope_split_kernel<<<(T*NH*HD + 255)/256, 256>>>(rope);

    // 3. Tensor-core block-diagonal flash attention (single fp16)
    attn_mma_kernel<<<dim3(T/64, NH), 128>>>(seg);

    // 4. out = att @ Wproj + b  (fp16, BK=64)
    gemm_f16_kernel<<<dim3(HID/BN, T/BM), 256, GEMM_SMEM>>>(
        p_att16, p_wp, projB, out, HID, HID);
}